// round 1
// baseline (speedup 1.0000x reference)
#include <cuda_runtime.h>

// ---------------------------------------------------------------------------
// Problem constants: B=131072, D=512, layer sizes 512 -> 512 -> 128 -> 32 -> 8 -> 1
// Inputs (metadata order):
//  0:x  1:W1 2:b1 3:g1 4:be1  5:W2 6:b2 7:g2 8:be2  9:W3 10:b3 11:g3 12:be3
//  13:W4 14:b4 15:g4 16:be4  17:Wh 18:bh 19:u
// ---------------------------------------------------------------------------

#define BATCH_MAX 131072

// Device-global scratch (allocation inside kernel_launch is forbidden).
__device__ float g_h1[BATCH_MAX * 512];   // 256 MiB
__device__ float g_h2[BATCH_MAX * 128];   //  64 MiB

typedef unsigned long long u64;

__device__ __forceinline__ u64 pack2(float lo, float hi) {
    u64 r;
    asm("mov.b64 %0, {%1, %2};" : "=l"(r) : "f"(lo), "f"(hi));
    return r;
}
__device__ __forceinline__ void unpack2(u64 v, float& lo, float& hi) {
    asm("mov.b64 {%0, %1}, %2;" : "=f"(lo), "=f"(hi) : "l"(v));
}
// Packed dual-FMA (sm_103a): 2 fp32 FMAs per instruction -> 2x scalar FFMA rate.
__device__ __forceinline__ u64 ffma2(u64 a, u64 b, u64 c) {
    u64 d;
    asm("fma.rn.f32x2 %0, %1, %2, %3;" : "=l"(d) : "l"(a), "l"(b), "l"(c));
    return d;
}

__device__ __forceinline__ float warp_sum(float v) {
#pragma unroll
    for (int o = 16; o; o >>= 1) v += __shfl_xor_sync(0xffffffffu, v, o);
    return v;
}

// ---------------------------------------------------------------------------
// C[M,N] = A[M,K] @ B[N,K]^T + bias   (A, B row-major; both contiguous along K)
// Tile: TM=64 x TN=128, KC=32. 256 threads, micro-tile 4m x 8n via f32x2 FMAs.
// Requires: M % 64 == 0, N % 128 == 0, K % 32 == 0 (true for all our shapes).
// ---------------------------------------------------------------------------
__global__ void __launch_bounds__(256)
gemm_bias_kernel(const float* __restrict__ A, const float* __restrict__ B,
                 const float* __restrict__ bias, float* __restrict__ C,
                 int N, int K)
{
    constexpr int TM = 64, TN = 128, KC = 32;
    __shared__ float As[KC][TM];   // transposed: conflict-free, vectorizable LDS
    __shared__ float Bs[KC][TN];

    const int tid = threadIdx.x;
    const int tx = tid & 15;            // n-position: 8 cols per thread
    const int ty = tid >> 4;            // m-position: 4 rows per thread
    const size_t rowBase = (size_t)blockIdx.y * TM;
    const int    colBase = blockIdx.x * TN;

    u64 acc[4][4];
#pragma unroll
    for (int i = 0; i < 4; i++)
#pragma unroll
        for (int j = 0; j < 4; j++) acc[i][j] = 0ULL;

    for (int k0 = 0; k0 < K; k0 += KC) {
        // A tile: 64x32 floats = 512 float4 -> 2 per thread
        {
            int idx = tid;
#pragma unroll
            for (int v = 0; v < 2; v++, idx += 256) {
                int m  = idx >> 3;      // / (KC/4)
                int kq = idx & 7;
                const float4 a = *reinterpret_cast<const float4*>(
                    A + (rowBase + m) * (size_t)K + k0 + kq * 4);
                As[kq * 4 + 0][m] = a.x; As[kq * 4 + 1][m] = a.y;
                As[kq * 4 + 2][m] = a.z; As[kq * 4 + 3][m] = a.w;
            }
        }
        // B tile: 128x32 floats = 1024 float4 -> 4 per thread
        {
            int idx = tid;
#pragma unroll
            for (int v = 0; v < 4; v++, idx += 256) {
                int n  = idx >> 3;
                int kq = idx & 7;
                const float4 b = *reinterpret_cast<const float4*>(
                    B + (size_t)(colBase + n) * K + k0 + kq * 4);
                Bs[kq * 4 + 0][n] = b.x; Bs[kq * 4 + 1][n] = b.y;
                Bs[kq * 4 + 2][n] = b.z; Bs[kq * 4 + 3][n] = b.w;
            }
        }
        __syncthreads();
#pragma unroll
        for (int k = 0; k < KC; k++) {
            const float4 a  = *reinterpret_cast<const float4*>(&As[k][ty * 4]);
            const float4 b0 = *reinterpret_cast<const float4*>(&Bs[k][tx * 8]);
            const float4 b1 = *reinterpret_cast<const float4*>(&Bs[k][tx * 8 + 4]);
            u64 bb[4] = { pack2(b0.x, b0.y), pack2(b0.z, b0.w),
                          pack2(b1.x, b1.y), pack2(b1.z, b1.w) };
            float av[4] = { a.x, a.y, a.z, a.w };
#pragma unroll
            for (int i = 0; i < 4; i++) {
                u64 aa = pack2(av[i], av[i]);
#pragma unroll
                for (int j = 0; j < 4; j++) acc[i][j] = ffma2(aa, bb[j], acc[i][j]);
            }
        }
        __syncthreads();
    }

    float bv[8];
#pragma unroll
    for (int j = 0; j < 8; j++) bv[j] = bias[colBase + tx * 8 + j];

#pragma unroll
    for (int i = 0; i < 4; i++) {
        float o[8];
#pragma unroll
        for (int j = 0; j < 4; j++) unpack2(acc[i][j], o[2 * j], o[2 * j + 1]);
        float4 r0 = make_float4(o[0] + bv[0], o[1] + bv[1], o[2] + bv[2], o[3] + bv[3]);
        float4 r1 = make_float4(o[4] + bv[4], o[5] + bv[5], o[6] + bv[6], o[7] + bv[7]);
        float* cp = C + (rowBase + ty * 4 + i) * (size_t)N + colBase + tx * 8;
        *reinterpret_cast<float4*>(cp)     = r0;
        *reinterpret_cast<float4*>(cp + 4) = r1;
    }
}

// ---------------------------------------------------------------------------
// In-place LayerNorm + CELU over last dim (warp per row, values in registers).
// var = mean((h-mu)^2) computed two-pass, matching the reference formula.
// ---------------------------------------------------------------------------
template <int NCOLS>
__global__ void __launch_bounds__(256)
ln_celu_kernel(float* __restrict__ h, const float* __restrict__ g,
               const float* __restrict__ be)
{
    constexpr int PER = NCOLS / 32;
    const int lane = threadIdx.x & 31;
    const size_t row = (size_t)blockIdx.x * 8 + (threadIdx.x >> 5);
    float* rowp = h + row * NCOLS;

    float v[PER];
    float s = 0.f;
#pragma unroll
    for (int i = 0; i < PER; i++) { v[i] = rowp[lane + 32 * i]; s += v[i]; }
    s = warp_sum(s);
    const float mu = s * (1.0f / NCOLS);

    float q = 0.f;
#pragma unroll
    for (int i = 0; i < PER; i++) { float d = v[i] - mu; q += d * d; }
    q = warp_sum(q);
    const float rstd = rsqrtf(q * (1.0f / NCOLS) + 1e-5f);

#pragma unroll
    for (int i = 0; i < PER; i++) {
        const int c = lane + 32 * i;
        float y = (v[i] - mu) * rstd * g[c] + be[c];
        rowp[c] = (y > 0.f) ? y : expm1f(y);
    }
}

// ---------------------------------------------------------------------------
// Tail: layer3 (128->32) + LN + CELU, layer4 (32->8) + LN + CELU,
//       spectral-norm head (exact eps-faithful sigma), one warp per row.
// ---------------------------------------------------------------------------
__global__ void __launch_bounds__(256)
tail_kernel(const float* __restrict__ h2,
            const float* __restrict__ W3, const float* __restrict__ b3,
            const float* __restrict__ g3, const float* __restrict__ be3,
            const float* __restrict__ W4, const float* __restrict__ b4,
            const float* __restrict__ g4, const float* __restrict__ be4,
            const float* __restrict__ Wh, const float* __restrict__ bh,
            const float* __restrict__ u, float* __restrict__ out)
{
    __shared__ float sW3[32 * 128];
    __shared__ float sW4[8 * 32];
    const int tid = threadIdx.x;
    for (int i = tid; i < 32 * 128; i += 256) sW3[i] = W3[i];
    if (tid < 8 * 32) sW4[tid] = W4[tid];
    __syncthreads();

    const int lane = tid & 31;
    const size_t row = (size_t)blockIdx.x * 8 + (tid >> 5);
    const float* rp = h2 + row * 128;
    const float r0 = rp[lane], r1 = rp[lane + 32], r2 = rp[lane + 64], r3 = rp[lane + 96];

    // Layer 3: 32 outputs, each a full-warp dot over 128 (4 values per lane).
    float h3 = 0.f;
#pragma unroll
    for (int j = 0; j < 32; j++) {
        const float* w = sW3 + j * 128;
        float p = r0 * w[lane] + r1 * w[lane + 32] + r2 * w[lane + 64] + r3 * w[lane + 96];
        p = warp_sum(p);
        if (lane == j) h3 = p + b3[j];
    }
    // LN(32) + CELU
    float mu  = warp_sum(h3) * (1.f / 32.f);
    float d   = h3 - mu;
    float var = warp_sum(d * d) * (1.f / 32.f);
    float y3  = d * rsqrtf(var + 1e-5f) * g3[lane] + be3[lane];
    const float c3 = (y3 > 0.f) ? y3 : expm1f(y3);

    // Layer 4: 8 outputs, dot over 32 (1 value per lane).
    float h4 = 0.f;
#pragma unroll
    for (int j = 0; j < 8; j++) {
        float p = warp_sum(c3 * sW4[j * 32 + lane]);
        if (lane == j) h4 = p + b4[j];
    }
    // LN(8) + CELU on lanes 0..7
    const bool act = (lane < 8);
    float hv = act ? h4 : 0.f;
    mu  = warp_sum(hv) * 0.125f;
    d   = act ? (h4 - mu) : 0.f;
    var = warp_sum(d * d) * 0.125f;
    float c4 = 0.f;
    if (act) {
        float y4 = d * rsqrtf(var + 1e-5f) * g4[lane] + be4[lane];
        c4 = (y4 > 0.f) ? y4 : expm1f(y4);
    }

    // Spectral norm sigma, eps-faithful to the reference power iteration.
    // For W of shape [1,8]: v = u0*w/(|u0|*||w||+eps); t = W@v; sigma = (t/(|t|+eps))*t
    const float wh  = act ? Wh[lane] : 0.f;
    const float nrm = sqrtf(warp_sum(wh * wh));
    const float u0  = u[0];
    const float vden = fabsf(u0) * nrm + 1e-12f;
    const float t    = u0 * nrm * nrm / vden;
    const float u2n  = t / (fabsf(t) + 1e-12f);
    const float sigma = u2n * t;

    float p = warp_sum(c4 * wh / sigma);
    if (lane == 0) out[row] = p + bh[0];
}

// ---------------------------------------------------------------------------
extern "C" void kernel_launch(void* const* d_in, const int* in_sizes, int n_in,
                              void* d_out, int out_size)
{
    const float* x   = (const float*)d_in[0];
    const float* W1  = (const float*)d_in[1];
    const float* b1  = (const float*)d_in[2];
    const float* g1  = (const float*)d_in[3];
    const float* be1 = (const float*)d_in[4];
    const float* W2  = (const float*)d_in[5];
    const float* b2  = (const float*)d_in[6];
    const float* g2  = (const float*)d_in[7];
    const float* be2 = (const float*)d_in[8];
    const float* W3  = (const float*)d_in[9];
    const float* b3  = (const float*)d_in[10];
    const float* g3  = (const float*)d_in[11];
    const float* be3 = (const float*)d_in[12];
    const float* W4  = (const float*)d_in[13];
    const float* b4  = (const float*)d_in[14];
    const float* g4  = (const float*)d_in[15];
    const float* be4 = (const float*)d_in[16];
    const float* Wh  = (const float*)d_in[17];
    const float* bh  = (const float*)d_in[18];
    const float* u   = (const float*)d_in[19];
    float* out = (float*)d_out;

    const int M = in_sizes[0] / 512;   // 131072

    float *h1, *h2;
    cudaGetSymbolAddress((void**)&h1, g_h1);
    cudaGetSymbolAddress((void**)&h2, g_h2);

    dim3 blk(256);

    // Layer 1: [M,512] @ [512,512]^T + b1
    gemm_bias_kernel<<<dim3(512 / 128, M / 64), blk>>>(x, W1, b1, h1, 512, 512);
    ln_celu_kernel<512><<<M / 8, blk>>>(h1, g1, be1);

    // Layer 2: [M,512] @ [128,512]^T + b2
    gemm_bias_kernel<<<dim3(128 / 128, M / 64), blk>>>(h1, W2, b2, h2, 128, 512);
    ln_celu_kernel<128><<<M / 8, blk>>>(h2, g2, be2);

    // Layers 3+4 + spectral-norm head, fused.
    tail_kernel<<<M / 8, blk>>>(h2, W3, b3, g3, be3, W4, b4, g4, be4, Wh, bh, u, out);
}

// round 3
// speedup vs baseline: 3.0564x; 3.0564x over previous
#include <cuda_runtime.h>
#include <cuda_bf16.h>
#include <cstdint>

// ---------------------------------------------------------------------------
// B=131072, chain 512 ->(W1)512 ->(W2)128 ->(W3)32 ->(W4)8 ->(Wh)1
// GEMM1/GEMM2: HMMA mma.sync bf16x3 (hi/lo split) — no 'a'-suffix features.
// LN+CELU as separate validated passes; tail kernel validated in R1.
// ---------------------------------------------------------------------------

#define BATCH 131072

__device__ __align__(256) __nv_bfloat16 g_xhi  [BATCH * 512];
__device__ __align__(256) __nv_bfloat16 g_xlo  [BATCH * 512];
__device__ __align__(256) float         g_h1raw[BATCH * 512];
__device__ __align__(256) __nv_bfloat16 g_h1hi [BATCH * 512];
__device__ __align__(256) __nv_bfloat16 g_h1lo [BATCH * 512];
__device__ __align__(256) float         g_h2   [BATCH * 128];
__device__ __align__(256) __nv_bfloat16 g_w1hi [512 * 512];
__device__ __align__(256) __nv_bfloat16 g_w1lo [512 * 512];
__device__ __align__(256) __nv_bfloat16 g_w2hi [128 * 512];
__device__ __align__(256) __nv_bfloat16 g_w2lo [128 * 512];

// ------------------------------ helpers ------------------------------------
__device__ __forceinline__ uint32_t smem_u32(const void* p) {
    uint32_t a;
    asm("{ .reg .u64 t; cvta.to.shared.u64 t, %1; cvt.u32.u64 %0, t; }"
        : "=r"(a) : "l"(p));
    return a;
}
__device__ __forceinline__ void cp_async16(uint32_t dst, const void* src) {
    asm volatile("cp.async.cg.shared.global [%0], [%1], 16;"
                 :: "r"(dst), "l"(src) : "memory");
}
#define CP_COMMIT() asm volatile("cp.async.commit_group;" ::: "memory")
#define CP_WAIT(n)  asm volatile("cp.async.wait_group %0;" :: "n"(n) : "memory")

__device__ __forceinline__ void ldmx4(uint32_t& r0, uint32_t& r1,
                                      uint32_t& r2, uint32_t& r3, uint32_t a) {
    asm volatile("ldmatrix.sync.aligned.m8n8.x4.shared.b16 {%0,%1,%2,%3}, [%4];"
                 : "=r"(r0), "=r"(r1), "=r"(r2), "=r"(r3) : "r"(a));
}
__device__ __forceinline__ void mma16816(float& c0, float& c1, float& c2, float& c3,
                                         uint32_t a0, uint32_t a1, uint32_t a2, uint32_t a3,
                                         uint32_t b0, uint32_t b1) {
    asm volatile("mma.sync.aligned.m16n8k16.row.col.f32.bf16.bf16.f32 "
                 "{%0,%1,%2,%3}, {%4,%5,%6,%7}, {%8,%9}, {%0,%1,%2,%3};"
                 : "+f"(c0), "+f"(c1), "+f"(c2), "+f"(c3)
                 : "r"(a0), "r"(a1), "r"(a2), "r"(a3), "r"(b0), "r"(b1));
}
__device__ __forceinline__ float warp_sum(float v) {
#pragma unroll
    for (int o = 16; o; o >>= 1) v += __shfl_xor_sync(0xffffffffu, v, o);
    return v;
}

// ---------------------------------------------------------------------------
// Split fp32 -> bf16 hi + bf16 lo (lo = bf16(v - hi)).
// ---------------------------------------------------------------------------
__global__ void __launch_bounds__(256)
split_kernel(const float* __restrict__ src, __nv_bfloat16* __restrict__ hi,
             __nv_bfloat16* __restrict__ lo, int n4)
{
    int i = blockIdx.x * blockDim.x + threadIdx.x;
    if (i >= n4) return;
    float4 v = reinterpret_cast<const float4*>(src)[i];
    __nv_bfloat16 h0 = __float2bfloat16(v.x), h1 = __float2bfloat16(v.y);
    __nv_bfloat16 h2 = __float2bfloat16(v.z), h3 = __float2bfloat16(v.w);
    __nv_bfloat162 a, b, c, d;
    a.x = h0; a.y = h1; b.x = h2; b.y = h3;
    c.x = __float2bfloat16(v.x - __bfloat162float(h0));
    c.y = __float2bfloat16(v.y - __bfloat162float(h1));
    d.x = __float2bfloat16(v.z - __bfloat162float(h2));
    d.y = __float2bfloat16(v.w - __bfloat162float(h3));
    reinterpret_cast<__nv_bfloat162*>(hi)[2 * i]     = a;
    reinterpret_cast<__nv_bfloat162*>(hi)[2 * i + 1] = b;
    reinterpret_cast<__nv_bfloat162*>(lo)[2 * i]     = c;
    reinterpret_cast<__nv_bfloat162*>(lo)[2 * i + 1] = d;
}

// ---------------------------------------------------------------------------
// HMMA bf16x3 GEMM: C[M,N] = A[M,512] @ B[N,512]^T + bias (fp32 out).
// CTA 128x128, 8 warps (2x4) of 64x32, K chunk 32, 2-stage cp.async pipeline.
// smem rows padded to 40 bf16 (80B) -> conflict-free ldmatrix.
// ---------------------------------------------------------------------------
__global__ void __launch_bounds__(256, 1)
hgemm3_kernel(const __nv_bfloat16* __restrict__ Ahi, const __nv_bfloat16* __restrict__ Alo,
              const __nv_bfloat16* __restrict__ Bhi, const __nv_bfloat16* __restrict__ Blo,
              const float* __restrict__ bias, float* __restrict__ C, int N)
{
    constexpr int K = 512;
    constexpr int NSTAGES = K / 32;          // 16
    constexpr int RB = 80;                   // smem row stride, bytes (32 bf16 + pad)
    constexpr int MAT = 128 * RB;            // one 128x32 tile: 10240 B
    constexpr int STG = 4 * MAT;             // Ahi,Alo,Bhi,Blo: 40960 B

    extern __shared__ char smem[];
    const uint32_t sb = smem_u32(smem);

    const int tid   = threadIdx.x;
    const int lane  = tid & 31;
    const int wid   = tid >> 5;
    const int warpM = wid >> 2;              // 0..1  (64-row slabs)
    const int warpN = wid & 3;               // 0..3  (32-col slabs)
    const size_t rowBase = (size_t)blockIdx.y * 128;
    const int    colBase = blockIdx.x * 128;

    // per-thread load slots: 2 chunks per matrix (128 rows x 4 chunks = 512)
    const int c0r = (tid) >> 2,        c0q = tid & 3;
    const int c1r = (tid + 256) >> 2,  c1q = tid & 3;   // (tid+256)&3 == tid&3

    float acc[4][4][4];
#pragma unroll
    for (int i = 0; i < 4; i++)
#pragma unroll
        for (int j = 0; j < 4; j++)
#pragma unroll
            for (int q = 0; q < 4; q++) acc[i][j][q] = 0.f;

    auto load_stage = [&](int t) {
        const int k0 = t * 32;
        const uint32_t s = sb + (t & 1) * STG;
        // A hi/lo
        {
            const size_t g0 = (rowBase + c0r) * K + k0 + c0q * 8;
            const size_t g1 = (rowBase + c1r) * K + k0 + c1q * 8;
            const uint32_t d0 = c0r * RB + c0q * 16;
            const uint32_t d1 = c1r * RB + c1q * 16;
            cp_async16(s + d0,           Ahi + g0);
            cp_async16(s + d1,           Ahi + g1);
            cp_async16(s + MAT + d0,     Alo + g0);
            cp_async16(s + MAT + d1,     Alo + g1);
        }
        // B hi/lo
        {
            const size_t g0 = (size_t)(colBase + c0r) * K + k0 + c0q * 8;
            const size_t g1 = (size_t)(colBase + c1r) * K + k0 + c1q * 8;
            const uint32_t d0 = c0r * RB + c0q * 16;
            const uint32_t d1 = c1r * RB + c1q * 16;
            cp_async16(s + 2 * MAT + d0, Bhi + g0);
            cp_async16(s + 2 * MAT + d1, Bhi + g1);
            cp_async16(s + 3 * MAT + d0, Blo + g0);
            cp_async16(s + 3 * MAT + d1, Blo + g1);
        }
        CP_COMMIT();
    };

    load_stage(0);

#pragma unroll 1
    for (int t = 0; t < NSTAGES; t++) {
        if (t + 1 < NSTAGES) { load_stage(t + 1); CP_WAIT(1); }
        else                 { CP_WAIT(0); }
        __syncthreads();

        const uint32_t s = sb + (t & 1) * STG;
#pragma unroll
        for (int ks = 0; ks < 2; ks++) {
            // ---- A fragments (hi & lo), 4 m-tiles each ----
            uint32_t ah[4][4], al[4][4];
            const uint32_t aoff = (warpM * 64 + (lane & 15)) * RB
                                + ks * 32 + (lane >> 4) * 16;
#pragma unroll
            for (int mt = 0; mt < 4; mt++) {
                const uint32_t adr = s + aoff + mt * 16 * RB;
                ldmx4(ah[mt][0], ah[mt][1], ah[mt][2], ah[mt][3], adr);
                ldmx4(al[mt][0], al[mt][1], al[mt][2], al[mt][3], adr + MAT);
            }
            // ---- B fragments (hi & lo), 4 n-tiles via 2 x4 loads each ----
            uint32_t bh[4][2], bl[4][2];
            const uint32_t brow = warpN * 32 + (lane & 7) + ((lane >> 4) & 1) * 8;
            const uint32_t boff = brow * RB + ks * 32 + ((lane >> 3) & 1) * 16;
#pragma unroll
            for (int pr = 0; pr < 2; pr++) {
                const uint32_t adr = s + 2 * MAT + boff + pr * 16 * RB;
                ldmx4(bh[2 * pr][0], bh[2 * pr][1], bh[2 * pr + 1][0], bh[2 * pr + 1][1], adr);
                ldmx4(bl[2 * pr][0], bl[2 * pr][1], bl[2 * pr + 1][0], bl[2 * pr + 1][1], adr + MAT);
            }
            // ---- 3 products: hi*hi, hi*lo, lo*hi ----
#pragma unroll
            for (int mt = 0; mt < 4; mt++)
#pragma unroll
                for (int nt = 0; nt < 4; nt++) {
                    float* c = acc[mt][nt];
                    mma16816(c[0], c[1], c[2], c[3],
                             ah[mt][0], ah[mt][1], ah[mt][2], ah[mt][3],
                             bh[nt][0], bh[nt][1]);
                    mma16816(c[0], c[1], c[2], c[3],
                             ah[mt][0], ah[mt][1], ah[mt][2], ah[mt][3],
                             bl[nt][0], bl[nt][1]);
                    mma16816(c[0], c[1], c[2], c[3],
                             al[mt][0], al[mt][1], al[mt][2], al[mt][3],
                             bh[nt][0], bh[nt][1]);
                }
        }
        __syncthreads();
    }

    // ---- epilogue: + bias, fp32 out ----
#pragma unroll
    for (int mt = 0; mt < 4; mt++) {
        const size_t r0 = rowBase + warpM * 64 + mt * 16 + (lane >> 2);
#pragma unroll
        for (int nt = 0; nt < 4; nt++) {
            const int col = colBase + warpN * 32 + nt * 8 + (lane & 3) * 2;
            const float b0 = bias[col], b1 = bias[col + 1];
            float* c = acc[mt][nt];
            *reinterpret_cast<float2*>(C + r0 * N + col) =
                make_float2(c[0] + b0, c[1] + b1);
            *reinterpret_cast<float2*>(C + (r0 + 8) * N + col) =
                make_float2(c[2] + b0, c[3] + b1);
        }
    }
}

// ---------------------------------------------------------------------------
// LN + CELU over 512 cols, write split bf16 hi/lo (GEMM2 input format).
// ---------------------------------------------------------------------------
__global__ void __launch_bounds__(256)
ln_celu_split512_kernel(const float* __restrict__ h, const float* __restrict__ g,
                        const float* __restrict__ be,
                        __nv_bfloat16* __restrict__ hi, __nv_bfloat16* __restrict__ lo)
{
    constexpr int NC = 512, PER = NC / 32;
    const int lane = threadIdx.x & 31;
    const size_t row = (size_t)blockIdx.x * 8 + (threadIdx.x >> 5);
    const float* rowp = h + row * NC;

    float v[PER];
    float s = 0.f;
#pragma unroll
    for (int i = 0; i < PER; i++) { v[i] = rowp[lane + 32 * i]; s += v[i]; }
    s = warp_sum(s);
    const float mu = s * (1.0f / NC);
    float q = 0.f;
#pragma unroll
    for (int i = 0; i < PER; i++) { float d = v[i] - mu; q += d * d; }
    q = warp_sum(q);
    const float rstd = rsqrtf(q * (1.0f / NC) + 1e-5f);

#pragma unroll
    for (int i = 0; i < PER; i++) {
        const int c = lane + 32 * i;
        float y = (v[i] - mu) * rstd * g[c] + be[c];
        float a = (y > 0.f) ? y : expm1f(y);
        __nv_bfloat16 ah = __float2bfloat16(a);
        hi[row * NC + c] = ah;
        lo[row * NC + c] = __float2bfloat16(a - __bfloat162float(ah));
    }
}

// ---------------------------------------------------------------------------
// In-place LN + CELU over 128 cols (validated R1).
// ---------------------------------------------------------------------------
__global__ void __launch_bounds__(256)
ln_celu128_kernel(float* __restrict__ h, const float* __restrict__ g,
                  const float* __restrict__ be)
{
    constexpr int NC = 128, PER = NC / 32;
    const int lane = threadIdx.x & 31;
    const size_t row = (size_t)blockIdx.x * 8 + (threadIdx.x >> 5);
    float* rowp = h + row * NC;

    float v[PER];
    float s = 0.f;
#pragma unroll
    for (int i = 0; i < PER; i++) { v[i] = rowp[lane + 32 * i]; s += v[i]; }
    s = warp_sum(s);
    const float mu = s * (1.0f / NC);
    float q = 0.f;
#pragma unroll
    for (int i = 0; i < PER; i++) { float d = v[i] - mu; q += d * d; }
    q = warp_sum(q);
    const float rstd = rsqrtf(q * (1.0f / NC) + 1e-5f);
#pragma unroll
    for (int i = 0; i < PER; i++) {
        const int c = lane + 32 * i;
        float y = (v[i] - mu) * rstd * g[c] + be[c];
        rowp[c] = (y > 0.f) ? y : expm1f(y);
    }
}

// ---------------------------------------------------------------------------
// Tail: layer3 (128->32)+LN+CELU, layer4 (32->8)+LN+CELU, spectral-norm head.
// (validated R1, rel_err 3.4e-7)
// ---------------------------------------------------------------------------
__global__ void __launch_bounds__(256)
tail_kernel(const float* __restrict__ h2,
            const float* __restrict__ W3, const float* __restrict__ b3,
            const float* __restrict__ g3, const float* __restrict__ be3,
            const float* __restrict__ W4, const float* __restrict__ b4,
            const float* __restrict__ g4, const float* __restrict__ be4,
            const float* __restrict__ Wh, const float* __restrict__ bh,
            const float* __restrict__ u, float* __restrict__ out)
{
    __shared__ float sW3[32 * 128];
    __shared__ float sW4[8 * 32];
    const int tid = threadIdx.x;
    for (int i = tid; i < 32 * 128; i += 256) sW3[i] = W3[i];
    if (tid < 8 * 32) sW4[tid] = W4[tid];
    __syncthreads();

    const int lane = tid & 31;
    const size_t row = (size_t)blockIdx.x * 8 + (tid >> 5);
    const float* rp = h2 + row * 128;
    const float r0 = rp[lane], r1 = rp[lane + 32], r2 = rp[lane + 64], r3 = rp[lane + 96];

    float h3 = 0.f;
#pragma unroll
    for (int j = 0; j < 32; j++) {
        const float* w = sW3 + j * 128;
        float p = r0 * w[lane] + r1 * w[lane + 32] + r2 * w[lane + 64] + r3 * w[lane + 96];
        p = warp_sum(p);
        if (lane == j) h3 = p + b3[j];
    }
    float mu  = warp_sum(h3) * (1.f / 32.f);
    float d   = h3 - mu;
    float var = warp_sum(d * d) * (1.f / 32.f);
    float y3  = d * rsqrtf(var + 1e-5f) * g3[lane] + be3[lane];
    const float c3 = (y3 > 0.f) ? y3 : expm1f(y3);

    float h4 = 0.f;
#pragma unroll
    for (int j = 0; j < 8; j++) {
        float p = warp_sum(c3 * sW4[j * 32 + lane]);
        if (lane == j) h4 = p + b4[j];
    }
    const bool act = (lane < 8);
    float hv = act ? h4 : 0.f;
    mu  = warp_sum(hv) * 0.125f;
    d   = act ? (h4 - mu) : 0.f;
    var = warp_sum(d * d) * 0.125f;
    float c4 = 0.f;
    if (act) {
        float y4 = d * rsqrtf(var + 1e-5f) * g4[lane] + be4[lane];
        c4 = (y4 > 0.f) ? y4 : expm1f(y4);
    }

    const float wh  = act ? Wh[lane] : 0.f;
    const float nrm = sqrtf(warp_sum(wh * wh));
    const float u0  = u[0];
    const float vden = fabsf(u0) * nrm + 1e-12f;
    const float t    = u0 * nrm * nrm / vden;
    const float u2n  = t / (fabsf(t) + 1e-12f);
    const float sigma = u2n * t;

    float p = warp_sum(c4 * wh / sigma);
    if (lane == 0) out[row] = p + bh[0];
}

// ---------------------------------------------------------------------------
extern "C" void kernel_launch(void* const* d_in, const int* in_sizes, int n_in,
                              void* d_out, int out_size)
{
    const float* x   = (const float*)d_in[0];
    const float* W1  = (const float*)d_in[1];
    const float* b1  = (const float*)d_in[2];
    const float* g1  = (const float*)d_in[3];
    const float* be1 = (const float*)d_in[4];
    const float* W2  = (const float*)d_in[5];
    const float* b2  = (const float*)d_in[6];
    const float* g2  = (const float*)d_in[7];
    const float* be2 = (const float*)d_in[8];
    const float* W3  = (const float*)d_in[9];
    const float* b3  = (const float*)d_in[10];
    const float* g3  = (const float*)d_in[11];
    const float* be3 = (const float*)d_in[12];
    const float* W4  = (const float*)d_in[13];
    const float* b4  = (const float*)d_in[14];
    const float* g4  = (const float*)d_in[15];
    const float* be4 = (const float*)d_in[16];
    const float* Wh  = (const float*)d_in[17];
    const float* bh  = (const float*)d_in[18];
    const float* u   = (const float*)d_in[19];
    float* out = (float*)d_out;

    const int M = in_sizes[0] / 512;   // 131072

    __nv_bfloat16 *xhi, *xlo, *h1hi, *h1lo, *w1hi, *w1lo, *w2hi, *w2lo;
    float *h1raw, *h2;
    cudaGetSymbolAddress((void**)&xhi,   g_xhi);
    cudaGetSymbolAddress((void**)&xlo,   g_xlo);
    cudaGetSymbolAddress((void**)&h1raw, g_h1raw);
    cudaGetSymbolAddress((void**)&h1hi,  g_h1hi);
    cudaGetSymbolAddress((void**)&h1lo,  g_h1lo);
    cudaGetSymbolAddress((void**)&h2,    g_h2);
    cudaGetSymbolAddress((void**)&w1hi,  g_w1hi);
    cudaGetSymbolAddress((void**)&w1lo,  g_w1lo);
    cudaGetSymbolAddress((void**)&w2hi,  g_w2hi);
    cudaGetSymbolAddress((void**)&w2lo,  g_w2lo);

    constexpr int SMEM = 2 * 4 * 128 * 80;   // 81920 B
    cudaFuncSetAttribute(hgemm3_kernel,
                         cudaFuncAttributeMaxDynamicSharedMemorySize, SMEM);

    // Split inputs to bf16 hi/lo
    const int n4x = M * 512 / 4;
    split_kernel<<<(n4x + 255) / 256, 256>>>(x, xhi, xlo, n4x);
    split_kernel<<<(512 * 512 / 4 + 255) / 256, 256>>>(W1, w1hi, w1lo, 512 * 512 / 4);
    split_kernel<<<(128 * 512 / 4 + 255) / 256, 256>>>(W2, w2hi, w2lo, 128 * 512 / 4);

    // Layer 1 GEMM -> raw fp32, then LN+CELU -> split bf16
    hgemm3_kernel<<<dim3(4, M / 128), 256, SMEM>>>(xhi, xlo, w1hi, w1lo, b1, h1raw, 512);
    ln_celu_split512_kernel<<<M / 8, 256>>>(h1raw, g1, be1, h1hi, h1lo);

    // Layer 2 GEMM -> raw fp32, then in-place LN+CELU
    hgemm3_kernel<<<dim3(1, M / 128), 256, SMEM>>>(h1hi, h1lo, w2hi, w2lo, b2, h2, 128);
    ln_celu128_kernel<<<M / 8, 256>>>(h2, g2, be2);

    // Layers 3+4 + spectral-norm head
    tail_kernel<<<M / 8, 256>>>(h2, W3, b3, g3, be3, W4, b4, g4, be4, Wh, bh, u, out);
}

// round 4
// speedup vs baseline: 3.3666x; 1.1015x over previous
#include <cuda_runtime.h>
#include <cuda_bf16.h>
#include <cstdint>

// ---------------------------------------------------------------------------
// B=131072, chain 512 ->(W1)512 ->(W2)128 ->(W3)32 ->(W4)8 ->(Wh)1
// GEMM1/GEMM2: HMMA mma.sync bf16x3 (hi/lo split), 2 CTAs/SM for latency hiding.
// ---------------------------------------------------------------------------

#define BATCH 131072

__device__ __align__(256) __nv_bfloat16 g_xhi  [BATCH * 512];
__device__ __align__(256) __nv_bfloat16 g_xlo  [BATCH * 512];
__device__ __align__(256) float         g_h1raw[BATCH * 512];
__device__ __align__(256) __nv_bfloat16 g_h1hi [BATCH * 512];
__device__ __align__(256) __nv_bfloat16 g_h1lo [BATCH * 512];
__device__ __align__(256) float         g_h2   [BATCH * 128];
__device__ __align__(256) __nv_bfloat16 g_w1hi [512 * 512];
__device__ __align__(256) __nv_bfloat16 g_w1lo [512 * 512];
__device__ __align__(256) __nv_bfloat16 g_w2hi [128 * 512];
__device__ __align__(256) __nv_bfloat16 g_w2lo [128 * 512];

// ------------------------------ helpers ------------------------------------
__device__ __forceinline__ uint32_t smem_u32(const void* p) {
    uint32_t a;
    asm("{ .reg .u64 t; cvta.to.shared.u64 t, %1; cvt.u32.u64 %0, t; }"
        : "=r"(a) : "l"(p));
    return a;
}
__device__ __forceinline__ void cp_async16(uint32_t dst, const void* src) {
    asm volatile("cp.async.cg.shared.global [%0], [%1], 16;"
                 :: "r"(dst), "l"(src) : "memory");
}
#define CP_COMMIT() asm volatile("cp.async.commit_group;" ::: "memory")
#define CP_WAIT(n)  asm volatile("cp.async.wait_group %0;" :: "n"(n) : "memory")

__device__ __forceinline__ void ldmx4(uint32_t& r0, uint32_t& r1,
                                      uint32_t& r2, uint32_t& r3, uint32_t a) {
    asm volatile("ldmatrix.sync.aligned.m8n8.x4.shared.b16 {%0,%1,%2,%3}, [%4];"
                 : "=r"(r0), "=r"(r1), "=r"(r2), "=r"(r3) : "r"(a));
}
__device__ __forceinline__ void mma16816(float& c0, float& c1, float& c2, float& c3,
                                         uint32_t a0, uint32_t a1, uint32_t a2, uint32_t a3,
                                         uint32_t b0, uint32_t b1) {
    asm volatile("mma.sync.aligned.m16n8k16.row.col.f32.bf16.bf16.f32 "
                 "{%0,%1,%2,%3}, {%4,%5,%6,%7}, {%8,%9}, {%0,%1,%2,%3};"
                 : "+f"(c0), "+f"(c1), "+f"(c2), "+f"(c3)
                 : "r"(a0), "r"(a1), "r"(a2), "r"(a3), "r"(b0), "r"(b1));
}
__device__ __forceinline__ float warp_sum(float v) {
#pragma unroll
    for (int o = 16; o; o >>= 1) v += __shfl_xor_sync(0xffffffffu, v, o);
    return v;
}

// ---------------------------------------------------------------------------
// Split fp32 -> bf16 hi + bf16 lo (lo = bf16(v - hi)).
// ---------------------------------------------------------------------------
__global__ void __launch_bounds__(256)
split_kernel(const float* __restrict__ src, __nv_bfloat16* __restrict__ hi,
             __nv_bfloat16* __restrict__ lo, int n4)
{
    int i = blockIdx.x * blockDim.x + threadIdx.x;
    if (i >= n4) return;
    float4 v = reinterpret_cast<const float4*>(src)[i];
    __nv_bfloat16 h0 = __float2bfloat16(v.x), h1 = __float2bfloat16(v.y);
    __nv_bfloat16 h2 = __float2bfloat16(v.z), h3 = __float2bfloat16(v.w);
    __nv_bfloat162 a, b, c, d;
    a.x = h0; a.y = h1; b.x = h2; b.y = h3;
    c.x = __float2bfloat16(v.x - __bfloat162float(h0));
    c.y = __float2bfloat16(v.y - __bfloat162float(h1));
    d.x = __float2bfloat16(v.z - __bfloat162float(h2));
    d.y = __float2bfloat16(v.w - __bfloat162float(h3));
    reinterpret_cast<__nv_bfloat162*>(hi)[2 * i]     = a;
    reinterpret_cast<__nv_bfloat162*>(hi)[2 * i + 1] = b;
    reinterpret_cast<__nv_bfloat162*>(lo)[2 * i]     = c;
    reinterpret_cast<__nv_bfloat162*>(lo)[2 * i + 1] = d;
}

// ---------------------------------------------------------------------------
// HMMA bf16x3 GEMM: C[M,N] = A[M,512] @ B[N,512]^T + bias (fp32 out).
// CTA 128x128, 8 warps (2x4) of 64x32, K chunk 32, 2-stage cp.async pipeline.
// __launch_bounds__(256, 2): cap regs at 128 so 2 CTAs/SM co-reside and the
// per-stage syncthreads/epilogue of one CTA hides under the other's MMAs.
// ---------------------------------------------------------------------------
__global__ void __launch_bounds__(256, 2)
hgemm3_kernel(const __nv_bfloat16* __restrict__ Ahi, const __nv_bfloat16* __restrict__ Alo,
              const __nv_bfloat16* __restrict__ Bhi, const __nv_bfloat16* __restrict__ Blo,
              const float* __restrict__ bias, float* __restrict__ C, int N)
{
    constexpr int K = 512;
    constexpr int NSTAGES = K / 32;          // 16
    constexpr int RB = 80;                   // smem row stride, bytes (32 bf16 + pad)
    constexpr int MAT = 128 * RB;            // one 128x32 tile: 10240 B
    constexpr int STG = 4 * MAT;             // Ahi,Alo,Bhi,Blo: 40960 B

    extern __shared__ char smem[];
    const uint32_t sb = smem_u32(smem);

    const int tid   = threadIdx.x;
    const int lane  = tid & 31;
    const int wid   = tid >> 5;
    const int warpM = wid >> 2;              // 0..1  (64-row slabs)
    const int warpN = wid & 3;               // 0..3  (32-col slabs)
    const size_t rowBase = (size_t)blockIdx.y * 128;
    const int    colBase = blockIdx.x * 128;

    // per-thread load slots: 2 chunks per matrix (128 rows x 4 chunks = 512)
    const int c0r = (tid) >> 2,        c0q = tid & 3;
    const int c1r = (tid + 256) >> 2,  c1q = tid & 3;

    float acc[4][4][4];
#pragma unroll
    for (int i = 0; i < 4; i++)
#pragma unroll
        for (int j = 0; j < 4; j++)
#pragma unroll
            for (int q = 0; q < 4; q++) acc[i][j][q] = 0.f;

    auto load_stage = [&](int t) {
        const int k0 = t * 32;
        const uint32_t s = sb + (t & 1) * STG;
        {
            const size_t g0 = (rowBase + c0r) * K + k0 + c0q * 8;
            const size_t g1 = (rowBase + c1r) * K + k0 + c1q * 8;
            const uint32_t d0 = c0r * RB + c0q * 16;
            const uint32_t d1 = c1r * RB + c1q * 16;
            cp_async16(s + d0,           Ahi + g0);
            cp_async16(s + d1,           Ahi + g1);
            cp_async16(s + MAT + d0,     Alo + g0);
            cp_async16(s + MAT + d1,     Alo + g1);
        }
        {
            const size_t g0 = (size_t)(colBase + c0r) * K + k0 + c0q * 8;
            const size_t g1 = (size_t)(colBase + c1r) * K + k0 + c1q * 8;
            const uint32_t d0 = c0r * RB + c0q * 16;
            const uint32_t d1 = c1r * RB + c1q * 16;
            cp_async16(s + 2 * MAT + d0, Bhi + g0);
            cp_async16(s + 2 * MAT + d1, Bhi + g1);
            cp_async16(s + 3 * MAT + d0, Blo + g0);
            cp_async16(s + 3 * MAT + d1, Blo + g1);
        }
        CP_COMMIT();
    };

    load_stage(0);

#pragma unroll 1
    for (int t = 0; t < NSTAGES; t++) {
        if (t + 1 < NSTAGES) { load_stage(t + 1); CP_WAIT(1); }
        else                 { CP_WAIT(0); }
        __syncthreads();

        const uint32_t s = sb + (t & 1) * STG;
#pragma unroll
        for (int ks = 0; ks < 2; ks++) {
            // ---- A fragments (hi & lo), 4 m-tiles each ----
            uint32_t ah[4][4], al[4][4];
            const uint32_t aoff = (warpM * 64 + (lane & 15)) * RB
                                + ks * 32 + (lane >> 4) * 16;
#pragma unroll
            for (int mt = 0; mt < 4; mt++) {
                const uint32_t adr = s + aoff + mt * 16 * RB;
                ldmx4(ah[mt][0], ah[mt][1], ah[mt][2], ah[mt][3], adr);
                ldmx4(al[mt][0], al[mt][1], al[mt][2], al[mt][3], adr + MAT);
            }
            // ---- B fragments per n-pair, consumed immediately (reg pressure) ----
            const uint32_t brow = warpN * 32 + (lane & 7) + ((lane >> 4) & 1) * 8;
            const uint32_t boff = brow * RB + ks * 32 + ((lane >> 3) & 1) * 16;
#pragma unroll
            for (int pr = 0; pr < 2; pr++) {
                uint32_t bh0, bh1, bh2, bh3, bl0, bl1, bl2, bl3;
                const uint32_t adr = s + 2 * MAT + boff + pr * 16 * RB;
                ldmx4(bh0, bh1, bh2, bh3, adr);
                ldmx4(bl0, bl1, bl2, bl3, adr + MAT);
#pragma unroll
                for (int mt = 0; mt < 4; mt++) {
                    float* c0 = acc[mt][2 * pr];
                    mma16816(c0[0], c0[1], c0[2], c0[3],
                             ah[mt][0], ah[mt][1], ah[mt][2], ah[mt][3], bh0, bh1);
                    mma16816(c0[0], c0[1], c0[2], c0[3],
                             ah[mt][0], ah[mt][1], ah[mt][2], ah[mt][3], bl0, bl1);
                    mma16816(c0[0], c0[1], c0[2], c0[3],
                             al[mt][0], al[mt][1], al[mt][2], al[mt][3], bh0, bh1);
                    float* c1 = acc[mt][2 * pr + 1];
                    mma16816(c1[0], c1[1], c1[2], c1[3],
                             ah[mt][0], ah[mt][1], ah[mt][2], ah[mt][3], bh2, bh3);
                    mma16816(c1[0], c1[1], c1[2], c1[3],
                             ah[mt][0], ah[mt][1], ah[mt][2], ah[mt][3], bl2, bl3);
                    mma16816(c1[0], c1[1], c1[2], c1[3],
                             al[mt][0], al[mt][1], al[mt][2], al[mt][3], bh2, bh3);
                }
            }
        }
        __syncthreads();
    }

    // ---- epilogue: + bias, fp32 out ----
#pragma unroll
    for (int mt = 0; mt < 4; mt++) {
        const size_t r0 = rowBase + warpM * 64 + mt * 16 + (lane >> 2);
#pragma unroll
        for (int nt = 0; nt < 4; nt++) {
            const int col = colBase + warpN * 32 + nt * 8 + (lane & 3) * 2;
            const float b0 = bias[col], b1 = bias[col + 1];
            float* c = acc[mt][nt];
            *reinterpret_cast<float2*>(C + r0 * N + col) =
                make_float2(c[0] + b0, c[1] + b1);
            *reinterpret_cast<float2*>(C + (r0 + 8) * N + col) =
                make_float2(c[2] + b0, c[3] + b1);
        }
    }
}

// ---------------------------------------------------------------------------
// LN + CELU over 512 cols, write split bf16 hi/lo (GEMM2 input format).
// ---------------------------------------------------------------------------
__global__ void __launch_bounds__(256)
ln_celu_split512_kernel(const float* __restrict__ h, const float* __restrict__ g,
                        const float* __restrict__ be,
                        __nv_bfloat16* __restrict__ hi, __nv_bfloat16* __restrict__ lo)
{
    constexpr int NC = 512, PER = NC / 32;
    const int lane = threadIdx.x & 31;
    const size_t row = (size_t)blockIdx.x * 8 + (threadIdx.x >> 5);
    const float* rowp = h + row * NC;

    float v[PER];
    float s = 0.f;
#pragma unroll
    for (int i = 0; i < PER; i++) { v[i] = rowp[lane + 32 * i]; s += v[i]; }
    s = warp_sum(s);
    const float mu = s * (1.0f / NC);
    float q = 0.f;
#pragma unroll
    for (int i = 0; i < PER; i++) { float d = v[i] - mu; q += d * d; }
    q = warp_sum(q);
    const float rstd = rsqrtf(q * (1.0f / NC) + 1e-5f);

#pragma unroll
    for (int i = 0; i < PER; i++) {
        const int c = lane + 32 * i;
        float y = (v[i] - mu) * rstd * g[c] + be[c];
        float a = (y > 0.f) ? y : expm1f(y);
        __nv_bfloat16 ah = __float2bfloat16(a);
        hi[row * NC + c] = ah;
        lo[row * NC + c] = __float2bfloat16(a - __bfloat162float(ah));
    }
}

// ---------------------------------------------------------------------------
// In-place LN + CELU over 128 cols (validated R1).
// ---------------------------------------------------------------------------
__global__ void __launch_bounds__(256)
ln_celu128_kernel(float* __restrict__ h, const float* __restrict__ g,
                  const float* __restrict__ be)
{
    constexpr int NC = 128, PER = NC / 32;
    const int lane = threadIdx.x & 31;
    const size_t row = (size_t)blockIdx.x * 8 + (threadIdx.x >> 5);
    float* rowp = h + row * NC;

    float v[PER];
    float s = 0.f;
#pragma unroll
    for (int i = 0; i < PER; i++) { v[i] = rowp[lane + 32 * i]; s += v[i]; }
    s = warp_sum(s);
    const float mu = s * (1.0f / NC);
    float q = 0.f;
#pragma unroll
    for (int i = 0; i < PER; i++) { float d = v[i] - mu; q += d * d; }
    q = warp_sum(q);
    const float rstd = rsqrtf(q * (1.0f / NC) + 1e-5f);
#pragma unroll
    for (int i = 0; i < PER; i++) {
        const int c = lane + 32 * i;
        float y = (v[i] - mu) * rstd * g[c] + be[c];
        rowp[c] = (y > 0.f) ? y : expm1f(y);
    }
}

// ---------------------------------------------------------------------------
// Tail: layer3 (128->32)+LN+CELU, layer4 (32->8)+LN+CELU, spectral-norm head.
// (validated R1, rel_err 3.4e-7)
// ---------------------------------------------------------------------------
__global__ void __launch_bounds__(256)
tail_kernel(const float* __restrict__ h2,
            const float* __restrict__ W3, const float* __restrict__ b3,
            const float* __restrict__ g3, const float* __restrict__ be3,
            const float* __restrict__ W4, const float* __restrict__ b4,
            const float* __restrict__ g4, const float* __restrict__ be4,
            const float* __restrict__ Wh, const float* __restrict__ bh,
            const float* __restrict__ u, float* __restrict__ out)
{
    __shared__ float sW3[32 * 128];
    __shared__ float sW4[8 * 32];
    const int tid = threadIdx.x;
    for (int i = tid; i < 32 * 128; i += 256) sW3[i] = W3[i];
    if (tid < 8 * 32) sW4[tid] = W4[tid];
    __syncthreads();

    const int lane = tid & 31;
    const size_t row = (size_t)blockIdx.x * 8 + (tid >> 5);
    const float* rp = h2 + row * 128;
    const float r0 = rp[lane], r1 = rp[lane + 32], r2 = rp[lane + 64], r3 = rp[lane + 96];

    float h3 = 0.f;
#pragma unroll
    for (int j = 0; j < 32; j++) {
        const float* w = sW3 + j * 128;
        float p = r0 * w[lane] + r1 * w[lane + 32] + r2 * w[lane + 64] + r3 * w[lane + 96];
        p = warp_sum(p);
        if (lane == j) h3 = p + b3[j];
    }
    float mu  = warp_sum(h3) * (1.f / 32.f);
    float d   = h3 - mu;
    float var = warp_sum(d * d) * (1.f / 32.f);
    float y3  = d * rsqrtf(var + 1e-5f) * g3[lane] + be3[lane];
    const float c3 = (y3 > 0.f) ? y3 : expm1f(y3);

    float h4 = 0.f;
#pragma unroll
    for (int j = 0; j < 8; j++) {
        float p = warp_sum(c3 * sW4[j * 32 + lane]);
        if (lane == j) h4 = p + b4[j];
    }
    const bool act = (lane < 8);
    float hv = act ? h4 : 0.f;
    mu  = warp_sum(hv) * 0.125f;
    d   = act ? (h4 - mu) : 0.f;
    var = warp_sum(d * d) * 0.125f;
    float c4 = 0.f;
    if (act) {
        float y4 = d * rsqrtf(var + 1e-5f) * g4[lane] + be4[lane];
        c4 = (y4 > 0.f) ? y4 : expm1f(y4);
    }

    const float wh  = act ? Wh[lane] : 0.f;
    const float nrm = sqrtf(warp_sum(wh * wh));
    const float u0  = u[0];
    const float vden = fabsf(u0) * nrm + 1e-12f;
    const float t    = u0 * nrm * nrm / vden;
    const float u2n  = t / (fabsf(t) + 1e-12f);
    const float sigma = u2n * t;

    float p = warp_sum(c4 * wh / sigma);
    if (lane == 0) out[row] = p + bh[0];
}

// ---------------------------------------------------------------------------
extern "C" void kernel_launch(void* const* d_in, const int* in_sizes, int n_in,
                              void* d_out, int out_size)
{
    const float* x   = (const float*)d_in[0];
    const float* W1  = (const float*)d_in[1];
    const float* b1  = (const float*)d_in[2];
    const float* g1  = (const float*)d_in[3];
    const float* be1 = (const float*)d_in[4];
    const float* W2  = (const float*)d_in[5];
    const float* b2  = (const float*)d_in[6];
    const float* g2  = (const float*)d_in[7];
    const float* be2 = (const float*)d_in[8];
    const float* W3  = (const float*)d_in[9];
    const float* b3  = (const float*)d_in[10];
    const float* g3  = (const float*)d_in[11];
    const float* be3 = (const float*)d_in[12];
    const float* W4  = (const float*)d_in[13];
    const float* b4  = (const float*)d_in[14];
    const float* g4  = (const float*)d_in[15];
    const float* be4 = (const float*)d_in[16];
    const float* Wh  = (const float*)d_in[17];
    const float* bh  = (const float*)d_in[18];
    const float* u   = (const float*)d_in[19];
    float* out = (float*)d_out;

    const int M = in_sizes[0] / 512;   // 131072

    __nv_bfloat16 *xhi, *xlo, *h1hi, *h1lo, *w1hi, *w1lo, *w2hi, *w2lo;
    float *h1raw, *h2;
    cudaGetSymbolAddress((void**)&xhi,   g_xhi);
    cudaGetSymbolAddress((void**)&xlo,   g_xlo);
    cudaGetSymbolAddress((void**)&h1raw, g_h1raw);
    cudaGetSymbolAddress((void**)&h1hi,  g_h1hi);
    cudaGetSymbolAddress((void**)&h1lo,  g_h1lo);
    cudaGetSymbolAddress((void**)&h2,    g_h2);
    cudaGetSymbolAddress((void**)&w1hi,  g_w1hi);
    cudaGetSymbolAddress((void**)&w1lo,  g_w1lo);
    cudaGetSymbolAddress((void**)&w2hi,  g_w2hi);
    cudaGetSymbolAddress((void**)&w2lo,  g_w2lo);

    constexpr int SMEM = 2 * 4 * 128 * 80;   // 81920 B
    cudaFuncSetAttribute(hgemm3_kernel,
                         cudaFuncAttributeMaxDynamicSharedMemorySize, SMEM);

    // Split inputs to bf16 hi/lo
    const int n4x = M * 512 / 4;
    split_kernel<<<(n4x + 255) / 256, 256>>>(x, xhi, xlo, n4x);
    split_kernel<<<(512 * 512 / 4 + 255) / 256, 256>>>(W1, w1hi, w1lo, 512 * 512 / 4);
    split_kernel<<<(128 * 512 / 4 + 255) / 256, 256>>>(W2, w2hi, w2lo, 128 * 512 / 4);

    // Layer 1 GEMM -> raw fp32, then LN+CELU -> split bf16
    hgemm3_kernel<<<dim3(4, M / 128), 256, SMEM>>>(xhi, xlo, w1hi, w1lo, b1, h1raw, 512);
    ln_celu_split512_kernel<<<M / 8, 256>>>(h1raw, g1, be1, h1hi, h1lo);

    // Layer 2 GEMM -> raw fp32, then in-place LN+CELU
    hgemm3_kernel<<<dim3(1, M / 128), 256, SMEM>>>(h1hi, h1lo, w2hi, w2lo, b2, h2, 128);
    ln_celu128_kernel<<<M / 8, 256>>>(h2, g2, be2);

    // Layers 3+4 + spectral-norm head
    tail_kernel<<<M / 8, 256>>>(h2, W3, b3, g3, be3, W4, b4, g4, be4, Wh, bh, u, out);
}

// round 5
// speedup vs baseline: 3.7011x; 1.0994x over previous
#include <cuda_runtime.h>
#include <cuda_bf16.h>
#include <cstdint>

// ---------------------------------------------------------------------------
// B=131072, chain 512 ->(W1)512 ->(W2)128 ->(W3)32 ->(W4)8 ->(Wh)1
// GEMM1/GEMM2: HMMA mma.sync bf16x3 (hi/lo split), 3-stage cp.async ring,
// XOR-swizzled smem (no padding), one __syncthreads per K-stage, 2 CTAs/SM.
// ---------------------------------------------------------------------------

#define BATCH 131072

__device__ __align__(256) __nv_bfloat16 g_xhi  [BATCH * 512];
__device__ __align__(256) __nv_bfloat16 g_xlo  [BATCH * 512];
__device__ __align__(256) float         g_h1raw[BATCH * 512];
__device__ __align__(256) __nv_bfloat16 g_h1hi [BATCH * 512];
__device__ __align__(256) __nv_bfloat16 g_h1lo [BATCH * 512];
__device__ __align__(256) float         g_h2   [BATCH * 128];
__device__ __align__(256) __nv_bfloat16 g_w1hi [512 * 512];
__device__ __align__(256) __nv_bfloat16 g_w1lo [512 * 512];
__device__ __align__(256) __nv_bfloat16 g_w2hi [128 * 512];
__device__ __align__(256) __nv_bfloat16 g_w2lo [128 * 512];

// ------------------------------ helpers ------------------------------------
__device__ __forceinline__ uint32_t smem_u32(const void* p) {
    uint32_t a;
    asm("{ .reg .u64 t; cvta.to.shared.u64 t, %1; cvt.u32.u64 %0, t; }"
        : "=r"(a) : "l"(p));
    return a;
}
__device__ __forceinline__ void cp_async16(uint32_t dst, const void* src) {
    asm volatile("cp.async.cg.shared.global [%0], [%1], 16;"
                 :: "r"(dst), "l"(src) : "memory");
}
#define CP_COMMIT() asm volatile("cp.async.commit_group;" ::: "memory")
#define CP_WAIT(n)  asm volatile("cp.async.wait_group %0;" :: "n"(n) : "memory")

__device__ __forceinline__ void ldmx4(uint32_t& r0, uint32_t& r1,
                                      uint32_t& r2, uint32_t& r3, uint32_t a) {
    asm volatile("ldmatrix.sync.aligned.m8n8.x4.shared.b16 {%0,%1,%2,%3}, [%4];"
                 : "=r"(r0), "=r"(r1), "=r"(r2), "=r"(r3) : "r"(a));
}
__device__ __forceinline__ void mma16816(float& c0, float& c1, float& c2, float& c3,
                                         uint32_t a0, uint32_t a1, uint32_t a2, uint32_t a3,
                                         uint32_t b0, uint32_t b1) {
    asm volatile("mma.sync.aligned.m16n8k16.row.col.f32.bf16.bf16.f32 "
                 "{%0,%1,%2,%3}, {%4,%5,%6,%7}, {%8,%9}, {%0,%1,%2,%3};"
                 : "+f"(c0), "+f"(c1), "+f"(c2), "+f"(c3)
                 : "r"(a0), "r"(a1), "r"(a2), "r"(a3), "r"(b0), "r"(b1));
}
__device__ __forceinline__ float warp_sum(float v) {
#pragma unroll
    for (int o = 16; o; o >>= 1) v += __shfl_xor_sync(0xffffffffu, v, o);
    return v;
}

// XOR swizzle for 64B rows of 4x16B chunks: conflict-free for ldmatrix's
// 8-row column reads AND cp.async row writes.  q' = q ^ ((row & 6) >> 1).
__device__ __forceinline__ uint32_t swz(uint32_t row, uint32_t q) {
    return row * 64 + (q ^ ((row & 6u) >> 1)) * 16;
}

// ---------------------------------------------------------------------------
// Split fp32 -> bf16 hi + bf16 lo (lo = bf16(v - hi)).
// ---------------------------------------------------------------------------
__global__ void __launch_bounds__(256)
split_kernel(const float* __restrict__ src, __nv_bfloat16* __restrict__ hi,
             __nv_bfloat16* __restrict__ lo, int n4)
{
    int i = blockIdx.x * blockDim.x + threadIdx.x;
    if (i >= n4) return;
    float4 v = reinterpret_cast<const float4*>(src)[i];
    __nv_bfloat16 h0 = __float2bfloat16(v.x), h1 = __float2bfloat16(v.y);
    __nv_bfloat16 h2 = __float2bfloat16(v.z), h3 = __float2bfloat16(v.w);
    __nv_bfloat162 a, b, c, d;
    a.x = h0; a.y = h1; b.x = h2; b.y = h3;
    c.x = __float2bfloat16(v.x - __bfloat162float(h0));
    c.y = __float2bfloat16(v.y - __bfloat162float(h1));
    d.x = __float2bfloat16(v.z - __bfloat162float(h2));
    d.y = __float2bfloat16(v.w - __bfloat162float(h3));
    reinterpret_cast<__nv_bfloat162*>(hi)[2 * i]     = a;
    reinterpret_cast<__nv_bfloat162*>(hi)[2 * i + 1] = b;
    reinterpret_cast<__nv_bfloat162*>(lo)[2 * i]     = c;
    reinterpret_cast<__nv_bfloat162*>(lo)[2 * i + 1] = d;
}

// ---------------------------------------------------------------------------
// HMMA bf16x3 GEMM: C[M,N] = A[M,512] @ B[N,512]^T + bias (fp32 out).
// CTA 128x128, 8 warps (2x4) each 64x32.  K chunk 32, 3-stage cp.async ring,
// XOR swizzle, ONE __syncthreads per stage.  2 CTAs/SM.
// ---------------------------------------------------------------------------
__global__ void __launch_bounds__(256, 2)
hgemm3_kernel(const __nv_bfloat16* __restrict__ Ahi, const __nv_bfloat16* __restrict__ Alo,
              const __nv_bfloat16* __restrict__ Bhi, const __nv_bfloat16* __restrict__ Blo,
              const float* __restrict__ bias, float* __restrict__ C, int N)
{
    constexpr int K = 512;
    constexpr int NSTAGES = K / 32;          // 16
    constexpr int MAT = 128 * 64;            // one 128x32 bf16 tile: 8192 B
    constexpr int STG = 4 * MAT;             // Ahi,Alo,Bhi,Blo: 32768 B
    constexpr int NBUF = 3;

    extern __shared__ char smem[];
    const uint32_t sb = smem_u32(smem);

    const int tid   = threadIdx.x;
    const int lane  = tid & 31;
    const int wid   = tid >> 5;
    const int warpM = wid >> 2;              // 0..1  (64-row slabs)
    const int warpN = wid & 3;               // 0..3  (32-col slabs)
    const size_t rowBase = (size_t)blockIdx.y * 128;
    const int    colBase = blockIdx.x * 128;

    // load slots: 512 16B-chunks per matrix, 2 per thread per matrix
    const int c0r = tid >> 2,       cq = tid & 3;
    const int c1r = 64 + (tid >> 2);
    const uint32_t d0 = swz(c0r, cq);
    const uint32_t d1 = swz(c1r, cq);

    float acc[4][4][4];
#pragma unroll
    for (int i = 0; i < 4; i++)
#pragma unroll
        for (int j = 0; j < 4; j++)
#pragma unroll
            for (int q = 0; q < 4; q++) acc[i][j][q] = 0.f;

    auto load_stage = [&](int t) {
        const int k0 = t * 32;
        const uint32_t s = sb + (t % NBUF) * STG;
        {
            const size_t g0 = (rowBase + c0r) * K + k0 + cq * 8;
            const size_t g1 = (rowBase + c1r) * K + k0 + cq * 8;
            cp_async16(s + d0,           Ahi + g0);
            cp_async16(s + d1,           Ahi + g1);
            cp_async16(s + MAT + d0,     Alo + g0);
            cp_async16(s + MAT + d1,     Alo + g1);
        }
        {
            const size_t g0 = (size_t)(colBase + c0r) * K + k0 + cq * 8;
            const size_t g1 = (size_t)(colBase + c1r) * K + k0 + cq * 8;
            cp_async16(s + 2 * MAT + d0, Bhi + g0);
            cp_async16(s + 2 * MAT + d1, Bhi + g1);
            cp_async16(s + 3 * MAT + d0, Blo + g0);
            cp_async16(s + 3 * MAT + d1, Blo + g1);
        }
        CP_COMMIT();
    };

    load_stage(0);
    load_stage(1);

#pragma unroll 1
    for (int t = 0; t < NSTAGES; t++) {
        if (t + 1 < NSTAGES) { CP_WAIT(1); } else { CP_WAIT(0); }
        __syncthreads();
        // prefetch stage t+2 into the buffer freed by compute(t-1)
        if (t + 2 < NSTAGES) load_stage(t + 2);

        const uint32_t s = sb + (t % NBUF) * STG;
#pragma unroll
        for (int ks = 0; ks < 2; ks++) {
            // ---- A fragments (hi & lo), 4 m-tiles each ----
            uint32_t ah[4][4], al[4][4];
            const uint32_t arow = warpM * 64 + (lane & 15);
            const uint32_t aq   = ks * 2 + (lane >> 4);
#pragma unroll
            for (int mt = 0; mt < 4; mt++) {
                const uint32_t adr = s + swz(arow + mt * 16, aq);
                ldmx4(ah[mt][0], ah[mt][1], ah[mt][2], ah[mt][3], adr);
                ldmx4(al[mt][0], al[mt][1], al[mt][2], al[mt][3], adr + MAT);
            }
            // ---- B fragments per n-pair, consumed immediately ----
            const uint32_t brow0 = warpN * 32 + (lane & 7) + ((lane >> 4) & 1) * 8;
            const uint32_t bq    = ks * 2 + ((lane >> 3) & 1);
#pragma unroll
            for (int pr = 0; pr < 2; pr++) {
                uint32_t bh0, bh1, bh2, bh3, bl0, bl1, bl2, bl3;
                const uint32_t adr = s + 2 * MAT + swz(brow0 + pr * 16, bq);
                ldmx4(bh0, bh1, bh2, bh3, adr);
                ldmx4(bl0, bl1, bl2, bl3, adr + MAT);
#pragma unroll
                for (int mt = 0; mt < 4; mt++) {
                    float* c0 = acc[mt][2 * pr];
                    mma16816(c0[0], c0[1], c0[2], c0[3],
                             ah[mt][0], ah[mt][1], ah[mt][2], ah[mt][3], bh0, bh1);
                    mma16816(c0[0], c0[1], c0[2], c0[3],
                             ah[mt][0], ah[mt][1], ah[mt][2], ah[mt][3], bl0, bl1);
                    mma16816(c0[0], c0[1], c0[2], c0[3],
                             al[mt][0], al[mt][1], al[mt][2], al[mt][3], bh0, bh1);
                    float* c1 = acc[mt][2 * pr + 1];
                    mma16816(c1[0], c1[1], c1[2], c1[3],
                             ah[mt][0], ah[mt][1], ah[mt][2], ah[mt][3], bh2, bh3);
                    mma16816(c1[0], c1[1], c1[2], c1[3],
                             ah[mt][0], ah[mt][1], ah[mt][2], ah[mt][3], bl2, bl3);
                    mma16816(c1[0], c1[1], c1[2], c1[3],
                             al[mt][0], al[mt][1], al[mt][2], al[mt][3], bh2, bh3);
                }
            }
        }
    }

    // ---- epilogue: + bias, fp32 out ----
#pragma unroll
    for (int mt = 0; mt < 4; mt++) {
        const size_t r0 = rowBase + warpM * 64 + mt * 16 + (lane >> 2);
#pragma unroll
        for (int nt = 0; nt < 4; nt++) {
            const int col = colBase + warpN * 32 + nt * 8 + (lane & 3) * 2;
            const float b0 = bias[col], b1 = bias[col + 1];
            float* c = acc[mt][nt];
            *reinterpret_cast<float2*>(C + r0 * N + col) =
                make_float2(c[0] + b0, c[1] + b1);
            *reinterpret_cast<float2*>(C + (r0 + 8) * N + col) =
                make_float2(c[2] + b0, c[3] + b1);
        }
    }
}

// ---------------------------------------------------------------------------
// LN + CELU over 512 cols, write split bf16 hi/lo (GEMM2 input format).
// ---------------------------------------------------------------------------
__global__ void __launch_bounds__(256)
ln_celu_split512_kernel(const float* __restrict__ h, const float* __restrict__ g,
                        const float* __restrict__ be,
                        __nv_bfloat16* __restrict__ hi, __nv_bfloat16* __restrict__ lo)
{
    constexpr int NC = 512, PER = NC / 32;
    const int lane = threadIdx.x & 31;
    const size_t row = (size_t)blockIdx.x * 8 + (threadIdx.x >> 5);
    const float* rowp = h + row * NC;

    float v[PER];
    float s = 0.f;
#pragma unroll
    for (int i = 0; i < PER; i++) { v[i] = rowp[lane + 32 * i]; s += v[i]; }
    s = warp_sum(s);
    const float mu = s * (1.0f / NC);
    float q = 0.f;
#pragma unroll
    for (int i = 0; i < PER; i++) { float d = v[i] - mu; q += d * d; }
    q = warp_sum(q);
    const float rstd = rsqrtf(q * (1.0f / NC) + 1e-5f);

#pragma unroll
    for (int i = 0; i < PER; i++) {
        const int c = lane + 32 * i;
        float y = (v[i] - mu) * rstd * g[c] + be[c];
        float a = (y > 0.f) ? y : expm1f(y);
        __nv_bfloat16 ah = __float2bfloat16(a);
        hi[row * NC + c] = ah;
        lo[row * NC + c] = __float2bfloat16(a - __bfloat162float(ah));
    }
}

// ---------------------------------------------------------------------------
// In-place LN + CELU over 128 cols.
// ---------------------------------------------------------------------------
__global__ void __launch_bounds__(256)
ln_celu128_kernel(float* __restrict__ h, const float* __restrict__ g,
                  const float* __restrict__ be)
{
    constexpr int NC = 128, PER = NC / 32;
    const int lane = threadIdx.x & 31;
    const size_t row = (size_t)blockIdx.x * 8 + (threadIdx.x >> 5);
    float* rowp = h + row * NC;

    float v[PER];
    float s = 0.f;
#pragma unroll
    for (int i = 0; i < PER; i++) { v[i] = rowp[lane + 32 * i]; s += v[i]; }
    s = warp_sum(s);
    const float mu = s * (1.0f / NC);
    float q = 0.f;
#pragma unroll
    for (int i = 0; i < PER; i++) { float d = v[i] - mu; q += d * d; }
    q = warp_sum(q);
    const float rstd = rsqrtf(q * (1.0f / NC) + 1e-5f);
#pragma unroll
    for (int i = 0; i < PER; i++) {
        const int c = lane + 32 * i;
        float y = (v[i] - mu) * rstd * g[c] + be[c];
        rowp[c] = (y > 0.f) ? y : expm1f(y);
    }
}

// ---------------------------------------------------------------------------
// Tail: layer3 (128->32)+LN+CELU, layer4 (32->8)+LN+CELU, spectral-norm head.
// ---------------------------------------------------------------------------
__global__ void __launch_bounds__(256)
tail_kernel(const float* __restrict__ h2,
            const float* __restrict__ W3, const float* __restrict__ b3,
            const float* __restrict__ g3, const float* __restrict__ be3,
            const float* __restrict__ W4, const float* __restrict__ b4,
            const float* __restrict__ g4, const float* __restrict__ be4,
            const float* __restrict__ Wh, const float* __restrict__ bh,
            const float* __restrict__ u, float* __restrict__ out)
{
    __shared__ float sW3[32 * 128];
    __shared__ float sW4[8 * 32];
    const int tid = threadIdx.x;
    for (int i = tid; i < 32 * 128; i += 256) sW3[i] = W3[i];
    if (tid < 8 * 32) sW4[tid] = W4[tid];
    __syncthreads();

    const int lane = tid & 31;
    const size_t row = (size_t)blockIdx.x * 8 + (tid >> 5);
    const float* rp = h2 + row * 128;
    const float r0 = rp[lane], r1 = rp[lane + 32], r2 = rp[lane + 64], r3 = rp[lane + 96];

    float h3 = 0.f;
#pragma unroll
    for (int j = 0; j < 32; j++) {
        const float* w = sW3 + j * 128;
        float p = r0 * w[lane] + r1 * w[lane + 32] + r2 * w[lane + 64] + r3 * w[lane + 96];
        p = warp_sum(p);
        if (lane == j) h3 = p + b3[j];
    }
    float mu  = warp_sum(h3) * (1.f / 32.f);
    float d   = h3 - mu;
    float var = warp_sum(d * d) * (1.f / 32.f);
    float y3  = d * rsqrtf(var + 1e-5f) * g3[lane] + be3[lane];
    const float c3 = (y3 > 0.f) ? y3 : expm1f(y3);

    float h4 = 0.f;
#pragma unroll
    for (int j = 0; j < 8; j++) {
        float p = warp_sum(c3 * sW4[j * 32 + lane]);
        if (lane == j) h4 = p + b4[j];
    }
    const bool act = (lane < 8);
    float hv = act ? h4 : 0.f;
    mu  = warp_sum(hv) * 0.125f;
    d   = act ? (h4 - mu) : 0.f;
    var = warp_sum(d * d) * 0.125f;
    float c4 = 0.f;
    if (act) {
        float y4 = d * rsqrtf(var + 1e-5f) * g4[lane] + be4[lane];
        c4 = (y4 > 0.f) ? y4 : expm1f(y4);
    }

    const float wh  = act ? Wh[lane] : 0.f;
    const float nrm = sqrtf(warp_sum(wh * wh));
    const float u0  = u[0];
    const float vden = fabsf(u0) * nrm + 1e-12f;
    const float t    = u0 * nrm * nrm / vden;
    const float u2n  = t / (fabsf(t) + 1e-12f);
    const float sigma = u2n * t;

    float p = warp_sum(c4 * wh / sigma);
    if (lane == 0) out[row] = p + bh[0];
}

// ---------------------------------------------------------------------------
extern "C" void kernel_launch(void* const* d_in, const int* in_sizes, int n_in,
                              void* d_out, int out_size)
{
    const float* x   = (const float*)d_in[0];
    const float* W1  = (const float*)d_in[1];
    const float* b1  = (const float*)d_in[2];
    const float* g1  = (const float*)d_in[3];
    const float* be1 = (const float*)d_in[4];
    const float* W2  = (const float*)d_in[5];
    const float* b2  = (const float*)d_in[6];
    const float* g2  = (const float*)d_in[7];
    const float* be2 = (const float*)d_in[8];
    const float* W3  = (const float*)d_in[9];
    const float* b3  = (const float*)d_in[10];
    const float* g3  = (const float*)d_in[11];
    const float* be3 = (const float*)d_in[12];
    const float* W4  = (const float*)d_in[13];
    const float* b4  = (const float*)d_in[14];
    const float* g4  = (const float*)d_in[15];
    const float* be4 = (const float*)d_in[16];
    const float* Wh  = (const float*)d_in[17];
    const float* bh  = (const float*)d_in[18];
    const float* u   = (const float*)d_in[19];
    float* out = (float*)d_out;

    const int M = in_sizes[0] / 512;   // 131072

    __nv_bfloat16 *xhi, *xlo, *h1hi, *h1lo, *w1hi, *w1lo, *w2hi, *w2lo;
    float *h1raw, *h2;
    cudaGetSymbolAddress((void**)&xhi,   g_xhi);
    cudaGetSymbolAddress((void**)&xlo,   g_xlo);
    cudaGetSymbolAddress((void**)&h1raw, g_h1raw);
    cudaGetSymbolAddress((void**)&h1hi,  g_h1hi);
    cudaGetSymbolAddress((void**)&h1lo,  g_h1lo);
    cudaGetSymbolAddress((void**)&h2,    g_h2);
    cudaGetSymbolAddress((void**)&w1hi,  g_w1hi);
    cudaGetSymbolAddress((void**)&w1lo,  g_w1lo);
    cudaGetSymbolAddress((void**)&w2hi,  g_w2hi);
    cudaGetSymbolAddress((void**)&w2lo,  g_w2lo);

    constexpr int SMEM = 3 * 4 * 128 * 64;   // 98304 B (3-stage ring)
    cudaFuncSetAttribute(hgemm3_kernel,
                         cudaFuncAttributeMaxDynamicSharedMemorySize, SMEM);

    // Split inputs to bf16 hi/lo
    const int n4x = M * 512 / 4;
    split_kernel<<<(n4x + 255) / 256, 256>>>(x, xhi, xlo, n4x);
    split_kernel<<<(512 * 512 / 4 + 255) / 256, 256>>>(W1, w1hi, w1lo, 512 * 512 / 4);
    split_kernel<<<(128 * 512 / 4 + 255) / 256, 256>>>(W2, w2hi, w2lo, 128 * 512 / 4);

    // Layer 1 GEMM -> raw fp32, then LN+CELU -> split bf16
    hgemm3_kernel<<<dim3(4, M / 128), 256, SMEM>>>(xhi, xlo, w1hi, w1lo, b1, h1raw, 512);
    ln_celu_split512_kernel<<<M / 8, 256>>>(h1raw, g1, be1, h1hi, h1lo);

    // Layer 2 GEMM -> raw fp32, then in-place LN+CELU
    hgemm3_kernel<<<dim3(1, M / 128), 256, SMEM>>>(h1hi, h1lo, w2hi, w2lo, b2, h2, 128);
    ln_celu128_kernel<<<M / 8, 256>>>(h2, g2, be2);

    // Layers 3+4 + spectral-norm head
    tail_kernel<<<M / 8, 256>>>(h2, W3, b3, g3, be3, W4, b4, g4, be4, Wh, bh, u, out);
}

// round 6
// speedup vs baseline: 3.7312x; 1.0081x over previous
#include <cuda_runtime.h>
#include <cuda_bf16.h>
#include <cstdint>

// ---------------------------------------------------------------------------
// B=131072, chain 512 ->(W1)512 ->(W2)128 ->(W3)32 ->(W4)8 ->(Wh)1
// GEMM1: HMMA bf16x3, 3-stage ring (R5) + per-colblock LN partial stats.
// GEMM2: fused — LN+CELU+split of h1 in prologue (fp32 staging), HMMA bf16x3,
//         LN+CELU of h2 in epilogue (full rows per CTA).
// ---------------------------------------------------------------------------

#define BATCH 131072

__device__ __align__(256) __nv_bfloat16 g_xhi  [BATCH * 512];
__device__ __align__(256) __nv_bfloat16 g_xlo  [BATCH * 512];
__device__ __align__(256) float         g_h1raw[BATCH * 512];
__device__ __align__(256) float         g_h2   [BATCH * 128];
__device__ __align__(256) float2        g_part [4 * BATCH];
__device__ __align__(256) __nv_bfloat16 g_w1hi [512 * 512];
__device__ __align__(256) __nv_bfloat16 g_w1lo [512 * 512];
__device__ __align__(256) __nv_bfloat16 g_w2hi [128 * 512];
__device__ __align__(256) __nv_bfloat16 g_w2lo [128 * 512];

// ------------------------------ helpers ------------------------------------
__device__ __forceinline__ uint32_t smem_u32(const void* p) {
    uint32_t a;
    asm("{ .reg .u64 t; cvta.to.shared.u64 t, %1; cvt.u32.u64 %0, t; }"
        : "=r"(a) : "l"(p));
    return a;
}
__device__ __forceinline__ void cp_async16(uint32_t dst, const void* src) {
    asm volatile("cp.async.cg.shared.global [%0], [%1], 16;"
                 :: "r"(dst), "l"(src) : "memory");
}
#define CP_COMMIT() asm volatile("cp.async.commit_group;" ::: "memory")
#define CP_WAIT(n)  asm volatile("cp.async.wait_group %0;" :: "n"(n) : "memory")

__device__ __forceinline__ void ldmx4(uint32_t& r0, uint32_t& r1,
                                      uint32_t& r2, uint32_t& r3, uint32_t a) {
    asm volatile("ldmatrix.sync.aligned.m8n8.x4.shared.b16 {%0,%1,%2,%3}, [%4];"
                 : "=r"(r0), "=r"(r1), "=r"(r2), "=r"(r3) : "r"(a));
}
__device__ __forceinline__ void mma16816(float& c0, float& c1, float& c2, float& c3,
                                         uint32_t a0, uint32_t a1, uint32_t a2, uint32_t a3,
                                         uint32_t b0, uint32_t b1) {
    asm volatile("mma.sync.aligned.m16n8k16.row.col.f32.bf16.bf16.f32 "
                 "{%0,%1,%2,%3}, {%4,%5,%6,%7}, {%8,%9}, {%0,%1,%2,%3};"
                 : "+f"(c0), "+f"(c1), "+f"(c2), "+f"(c3)
                 : "r"(a0), "r"(a1), "r"(a2), "r"(a3), "r"(b0), "r"(b1));
}
__device__ __forceinline__ float warp_sum(float v) {
#pragma unroll
    for (int o = 16; o; o >>= 1) v += __shfl_xor_sync(0xffffffffu, v, o);
    return v;
}

// XOR swizzle for 64B bf16 rows (4x16B chunks)
__device__ __forceinline__ uint32_t swz(uint32_t row, uint32_t q) {
    return row * 64 + (q ^ ((row & 6u) >> 1)) * 16;
}
// XOR swizzle for 128B fp32 rows (8x16B chunks)
__device__ __forceinline__ uint32_t swzf(uint32_t row, uint32_t q) {
    return row * 128 + (q ^ (row & 7u)) * 16;
}

__device__ __forceinline__ float celu1(float y) {
    return (y > 0.f) ? y : expm1f(y);
}

// ---------------------------------------------------------------------------
// Split fp32 -> bf16 hi + bf16 lo (lo = bf16(v - hi)).
// ---------------------------------------------------------------------------
__global__ void __launch_bounds__(256)
split_kernel(const float* __restrict__ src, __nv_bfloat16* __restrict__ hi,
             __nv_bfloat16* __restrict__ lo, int n4)
{
    int i = blockIdx.x * blockDim.x + threadIdx.x;
    if (i >= n4) return;
    float4 v = reinterpret_cast<const float4*>(src)[i];
    __nv_bfloat16 h0 = __float2bfloat16(v.x), h1 = __float2bfloat16(v.y);
    __nv_bfloat16 h2 = __float2bfloat16(v.z), h3 = __float2bfloat16(v.w);
    __nv_bfloat162 a, b, c, d;
    a.x = h0; a.y = h1; b.x = h2; b.y = h3;
    c.x = __float2bfloat16(v.x - __bfloat162float(h0));
    c.y = __float2bfloat16(v.y - __bfloat162float(h1));
    d.x = __float2bfloat16(v.z - __bfloat162float(h2));
    d.y = __float2bfloat16(v.w - __bfloat162float(h3));
    reinterpret_cast<__nv_bfloat162*>(hi)[2 * i]     = a;
    reinterpret_cast<__nv_bfloat162*>(hi)[2 * i + 1] = b;
    reinterpret_cast<__nv_bfloat162*>(lo)[2 * i]     = c;
    reinterpret_cast<__nv_bfloat162*>(lo)[2 * i + 1] = d;
}

// ---------------------------------------------------------------------------
// GEMM1: C[M,512] = A[M,512] @ B[512,512]^T + bias (fp32), bf16x3 HMMA.
// 3-stage cp.async ring, 1 sync/stage (R5).  NEW: epilogue also reduces
// per-row (sum, ssq) over this CTA's 128 cols -> g_part[blockIdx.x][row].
// ---------------------------------------------------------------------------
__global__ void __launch_bounds__(256, 2)
hgemm3_kernel(const __nv_bfloat16* __restrict__ Ahi, const __nv_bfloat16* __restrict__ Alo,
              const __nv_bfloat16* __restrict__ Bhi, const __nv_bfloat16* __restrict__ Blo,
              const float* __restrict__ bias, float* __restrict__ C,
              float2* __restrict__ gpart, int N, int Mtot)
{
    constexpr int K = 512;
    constexpr int NSTAGES = K / 32;
    constexpr int MAT = 128 * 64;            // 8192 B
    constexpr int STG = 4 * MAT;             // 32768 B
    constexpr int NBUF = 3;

    extern __shared__ char smem[];
    __shared__ float2 sred[4][128];
    const uint32_t sb = smem_u32(smem);

    const int tid   = threadIdx.x;
    const int lane  = tid & 31;
    const int wid   = tid >> 5;
    const int warpM = wid >> 2;
    const int warpN = wid & 3;
    const size_t rowBase = (size_t)blockIdx.y * 128;
    const int    colBase = blockIdx.x * 128;

    const int c0r = tid >> 2,  cq = tid & 3;
    const int c1r = 64 + (tid >> 2);
    const uint32_t d0 = swz(c0r, cq);
    const uint32_t d1 = swz(c1r, cq);

    float acc[4][4][4];
#pragma unroll
    for (int i = 0; i < 4; i++)
#pragma unroll
        for (int j = 0; j < 4; j++)
#pragma unroll
            for (int q = 0; q < 4; q++) acc[i][j][q] = 0.f;

    auto load_stage = [&](int t) {
        const int k0 = t * 32;
        const uint32_t s = sb + (t % NBUF) * STG;
        {
            const size_t g0 = (rowBase + c0r) * K + k0 + cq * 8;
            const size_t g1 = (rowBase + c1r) * K + k0 + cq * 8;
            cp_async16(s + d0,           Ahi + g0);
            cp_async16(s + d1,           Ahi + g1);
            cp_async16(s + MAT + d0,     Alo + g0);
            cp_async16(s + MAT + d1,     Alo + g1);
        }
        {
            const size_t g0 = (size_t)(colBase + c0r) * K + k0 + cq * 8;
            const size_t g1 = (size_t)(colBase + c1r) * K + k0 + cq * 8;
            cp_async16(s + 2 * MAT + d0, Bhi + g0);
            cp_async16(s + 2 * MAT + d1, Bhi + g1);
            cp_async16(s + 3 * MAT + d0, Blo + g0);
            cp_async16(s + 3 * MAT + d1, Blo + g1);
        }
        CP_COMMIT();
    };

    load_stage(0);
    load_stage(1);

#pragma unroll 1
    for (int t = 0; t < NSTAGES; t++) {
        if (t + 1 < NSTAGES) { CP_WAIT(1); } else { CP_WAIT(0); }
        __syncthreads();
        if (t + 2 < NSTAGES) load_stage(t + 2);

        const uint32_t s = sb + (t % NBUF) * STG;
#pragma unroll
        for (int ks = 0; ks < 2; ks++) {
            uint32_t ah[4][4], al[4][4];
            const uint32_t arow = warpM * 64 + (lane & 15);
            const uint32_t aq   = ks * 2 + (lane >> 4);
#pragma unroll
            for (int mt = 0; mt < 4; mt++) {
                const uint32_t adr = s + swz(arow + mt * 16, aq);
                ldmx4(ah[mt][0], ah[mt][1], ah[mt][2], ah[mt][3], adr);
                ldmx4(al[mt][0], al[mt][1], al[mt][2], al[mt][3], adr + MAT);
            }
            const uint32_t brow0 = warpN * 32 + (lane & 7) + ((lane >> 4) & 1) * 8;
            const uint32_t bq    = ks * 2 + ((lane >> 3) & 1);
#pragma unroll
            for (int pr = 0; pr < 2; pr++) {
                uint32_t bh0, bh1, bh2, bh3, bl0, bl1, bl2, bl3;
                const uint32_t adr = s + 2 * MAT + swz(brow0 + pr * 16, bq);
                ldmx4(bh0, bh1, bh2, bh3, adr);
                ldmx4(bl0, bl1, bl2, bl3, adr + MAT);
#pragma unroll
                for (int mt = 0; mt < 4; mt++) {
                    float* c0 = acc[mt][2 * pr];
                    mma16816(c0[0], c0[1], c0[2], c0[3],
                             ah[mt][0], ah[mt][1], ah[mt][2], ah[mt][3], bh0, bh1);
                    mma16816(c0[0], c0[1], c0[2], c0[3],
                             ah[mt][0], ah[mt][1], ah[mt][2], ah[mt][3], bl0, bl1);
                    mma16816(c0[0], c0[1], c0[2], c0[3],
                             al[mt][0], al[mt][1], al[mt][2], al[mt][3], bh0, bh1);
                    float* c1 = acc[mt][2 * pr + 1];
                    mma16816(c1[0], c1[1], c1[2], c1[3],
                             ah[mt][0], ah[mt][1], ah[mt][2], ah[mt][3], bh2, bh3);
                    mma16816(c1[0], c1[1], c1[2], c1[3],
                             ah[mt][0], ah[mt][1], ah[mt][2], ah[mt][3], bl2, bl3);
                    mma16816(c1[0], c1[1], c1[2], c1[3],
                             al[mt][0], al[mt][1], al[mt][2], al[mt][3], bh2, bh3);
                }
            }
        }
    }

    // ---- epilogue: + bias, fp32 out, per-row partial (sum, ssq) ----
#pragma unroll
    for (int mt = 0; mt < 4; mt++) {
        const int rloc = warpM * 64 + mt * 16 + (lane >> 2);
        const size_t r0 = rowBase + rloc;
        float s0 = 0.f, q0 = 0.f, s1 = 0.f, q1 = 0.f;
#pragma unroll
        for (int nt = 0; nt < 4; nt++) {
            const int col = colBase + warpN * 32 + nt * 8 + (lane & 3) * 2;
            const float b0 = bias[col], b1 = bias[col + 1];
            float* c = acc[mt][nt];
            const float v00 = c[0] + b0, v01 = c[1] + b1;
            const float v10 = c[2] + b0, v11 = c[3] + b1;
            *reinterpret_cast<float2*>(C + r0 * N + col)       = make_float2(v00, v01);
            *reinterpret_cast<float2*>(C + (r0 + 8) * N + col) = make_float2(v10, v11);
            s0 += v00 + v01; q0 += v00 * v00 + v01 * v01;
            s1 += v10 + v11; q1 += v10 * v10 + v11 * v11;
        }
        // reduce over the 4 lanes (lane&3) sharing each row
#pragma unroll
        for (int o = 1; o <= 2; o <<= 1) {
            s0 += __shfl_xor_sync(0xffffffffu, s0, o);
            q0 += __shfl_xor_sync(0xffffffffu, q0, o);
            s1 += __shfl_xor_sync(0xffffffffu, s1, o);
            q1 += __shfl_xor_sync(0xffffffffu, q1, o);
        }
        if ((lane & 3) == 0) {
            sred[warpN][rloc]     = make_float2(s0, q0);
            sred[warpN][rloc + 8] = make_float2(s1, q1);
        }
    }
    __syncthreads();
    if (tid < 128) {
        float s = 0.f, q = 0.f;
#pragma unroll
        for (int w = 0; w < 4; w++) { s += sred[w][tid].x; q += sred[w][tid].y; }
        gpart[(size_t)blockIdx.x * Mtot + rowBase + tid] = make_float2(s, q);
    }
}

// ---------------------------------------------------------------------------
// GEMM2 fused: h2 = LN2(CELU?no) ... computes
//   a1 = celu(LN1(h1raw))          (prologue, per K-stage, bf16 hi/lo split)
//   h2raw = a1 @ W2^T + b2         (HMMA bf16x3)
//   h2   = celu(LN2(h2raw))        (epilogue, full 128-col rows per CTA)
// ---------------------------------------------------------------------------
__global__ void __launch_bounds__(256, 2)
gemm2_fused_kernel(const float* __restrict__ h1raw, const float2* __restrict__ gpart,
                   const float* __restrict__ g1, const float* __restrict__ be1,
                   const __nv_bfloat16* __restrict__ Bhi, const __nv_bfloat16* __restrict__ Blo,
                   const float* __restrict__ b2, const float* __restrict__ g2,
                   const float* __restrict__ be2,
                   float* __restrict__ h2, int Mtot)
{
    constexpr int K = 512;
    constexpr int NSTAGES = K / 32;
    constexpr int MATB = 128 * 64;                 // 8192 B
    constexpr int OFF_AHI = 16384;                 // after fp32 staging
    constexpr int OFF_ALO = OFF_AHI + MATB;
    constexpr int OFF_BHI = OFF_ALO + MATB;
    constexpr int OFF_BLO = OFF_BHI + MATB;
    constexpr int STG = OFF_BLO + MATB;            // 49152 B

    extern __shared__ char smem[];
    __shared__ float  smu[128], srstd[128];
    __shared__ float  sg1[512], sbe1[512];
    __shared__ float  sg2[128], sbe2[128], sb2[128];
    __shared__ float2 sred[4][128];
    const uint32_t sb = smem_u32(smem);

    const int tid   = threadIdx.x;
    const int lane  = tid & 31;
    const int wid   = tid >> 5;
    const int warpM = wid >> 2;
    const int warpN = wid & 3;
    const size_t rowBase = (size_t)blockIdx.x * 128;

    // ---- prologue: finalize LN1 stats, cache LN params ----
    if (tid < 128) {
        float s = 0.f, q = 0.f;
#pragma unroll
        for (int b = 0; b < 4; b++) {
            float2 p = gpart[(size_t)b * Mtot + rowBase + tid];
            s += p.x; q += p.y;
        }
        const float mu = s * (1.f / 512.f);
        smu[tid]   = mu;
        srstd[tid] = rsqrtf(q * (1.f / 512.f) - mu * mu + 1e-5f);
        sg2[tid] = g2[tid]; sbe2[tid] = be2[tid]; sb2[tid] = b2[tid];
    }
#pragma unroll
    for (int i = tid; i < 512; i += 256) { sg1[i] = g1[i]; sbe1[i] = be1[i]; }
    __syncthreads();

    // B-load slots (bf16 tiles)
    const int c0r = tid >> 2,  cq = tid & 3;
    const int c1r = 64 + (tid >> 2);
    const uint32_t d0 = swz(c0r, cq);
    const uint32_t d1 = swz(c1r, cq);

    float acc[4][4][4];
#pragma unroll
    for (int i = 0; i < 4; i++)
#pragma unroll
        for (int j = 0; j < 4; j++)
#pragma unroll
            for (int q = 0; q < 4; q++) acc[i][j][q] = 0.f;

    auto load_stage = [&](int t) {
        const int k0 = t * 32;
        const uint32_t s = sb + (t & 1) * STG;
        // A staging: 128 rows x 32 fp32 = 1024 16B-chunks, 4 per thread
#pragma unroll
        for (int j = 0; j < 4; j++) {
            const int c = tid + j * 256;
            const int row = c >> 3, q = c & 7;
            cp_async16(s + swzf(row, q),
                       h1raw + (rowBase + row) * K + k0 + q * 4);
        }
        // B hi/lo
        {
            const size_t g0 = (size_t)c0r * K + k0 + cq * 8;
            const size_t g1 = (size_t)c1r * K + k0 + cq * 8;
            cp_async16(s + OFF_BHI + d0, Bhi + g0);
            cp_async16(s + OFF_BHI + d1, Bhi + g1);
            cp_async16(s + OFF_BLO + d0, Blo + g0);
            cp_async16(s + OFF_BLO + d1, Blo + g1);
        }
        CP_COMMIT();
    };

    load_stage(0);

#pragma unroll 1
    for (int t = 0; t < NSTAGES; t++) {
        CP_WAIT(0);
        __syncthreads();
        if (t + 1 < NSTAGES) load_stage(t + 1);

        const uint32_t s = sb + (t & 1) * STG;
        // ---- convert: LN1 + CELU + bf16 split, staging -> Ahi/Alo tiles ----
        {
            const int row  = tid >> 1;
            const int half = tid & 1;
            const float mu = smu[row], rs = srstd[row];
            const int k0 = t * 32;
            float4 f[4];
#pragma unroll
            for (int j = 0; j < 4; j++)
                f[j] = *reinterpret_cast<float4*>(smem + (t & 1) * STG +
                                                  swzf(row, half * 4 + j));
            uint32_t hw[8], lw[8];
#pragma unroll
            for (int j = 0; j < 4; j++) {
                const float vv[4] = { f[j].x, f[j].y, f[j].z, f[j].w };
                uint32_t hp[2], lp[2];
#pragma unroll
                for (int e2 = 0; e2 < 2; e2++) {
                    const int col0 = half * 16 + j * 4 + e2 * 2;
                    float a0 = celu1((vv[e2*2]   - mu) * rs * sg1[k0+col0]   + sbe1[k0+col0]);
                    float a1 = celu1((vv[e2*2+1] - mu) * rs * sg1[k0+col0+1] + sbe1[k0+col0+1]);
                    __nv_bfloat16 h0 = __float2bfloat16(a0);
                    __nv_bfloat16 h1b = __float2bfloat16(a1);
                    __nv_bfloat16 l0 = __float2bfloat16(a0 - __bfloat162float(h0));
                    __nv_bfloat16 l1 = __float2bfloat16(a1 - __bfloat162float(h1b));
                    hp[e2] = (uint32_t)__bfloat16_as_ushort(h1b) << 16 |
                             (uint32_t)__bfloat16_as_ushort(h0);
                    lp[e2] = (uint32_t)__bfloat16_as_ushort(l1) << 16 |
                             (uint32_t)__bfloat16_as_ushort(l0);
                }
                hw[j * 2] = hp[0]; hw[j * 2 + 1] = hp[1];
                lw[j * 2] = lp[0]; lw[j * 2 + 1] = lp[1];
            }
            const uint32_t q2 = half * 2;
            *reinterpret_cast<uint4*>(smem + (t & 1) * STG + OFF_AHI + swz(row, q2)) =
                make_uint4(hw[0], hw[1], hw[2], hw[3]);
            *reinterpret_cast<uint4*>(smem + (t & 1) * STG + OFF_AHI + swz(row, q2 + 1)) =
                make_uint4(hw[4], hw[5], hw[6], hw[7]);
            *reinterpret_cast<uint4*>(smem + (t & 1) * STG + OFF_ALO + swz(row, q2)) =
                make_uint4(lw[0], lw[1], lw[2], lw[3]);
            *reinterpret_cast<uint4*>(smem + (t & 1) * STG + OFF_ALO + swz(row, q2 + 1)) =
                make_uint4(lw[4], lw[5], lw[6], lw[7]);
        }
        __syncthreads();

        // ---- MMA ----
#pragma unroll
        for (int ks = 0; ks < 2; ks++) {
            uint32_t ah[4][4], al[4][4];
            const uint32_t arow = warpM * 64 + (lane & 15);
            const uint32_t aq   = ks * 2 + (lane >> 4);
#pragma unroll
            for (int mt = 0; mt < 4; mt++) {
                const uint32_t adr = s + OFF_AHI + swz(arow + mt * 16, aq);
                ldmx4(ah[mt][0], ah[mt][1], ah[mt][2], ah[mt][3], adr);
                ldmx4(al[mt][0], al[mt][1], al[mt][2], al[mt][3], adr + MATB);
            }
            const uint32_t brow0 = warpN * 32 + (lane & 7) + ((lane >> 4) & 1) * 8;
            const uint32_t bq    = ks * 2 + ((lane >> 3) & 1);
#pragma unroll
            for (int pr = 0; pr < 2; pr++) {
                uint32_t bh0, bh1, bh2, bh3, bl0, bl1, bl2, bl3;
                const uint32_t adr = s + OFF_BHI + swz(brow0 + pr * 16, bq);
                ldmx4(bh0, bh1, bh2, bh3, adr);
                ldmx4(bl0, bl1, bl2, bl3, adr + MATB);
#pragma unroll
                for (int mt = 0; mt < 4; mt++) {
                    float* c0 = acc[mt][2 * pr];
                    mma16816(c0[0], c0[1], c0[2], c0[3],
                             ah[mt][0], ah[mt][1], ah[mt][2], ah[mt][3], bh0, bh1);
                    mma16816(c0[0], c0[1], c0[2], c0[3],
                             ah[mt][0], ah[mt][1], ah[mt][2], ah[mt][3], bl0, bl1);
                    mma16816(c0[0], c0[1], c0[2], c0[3],
                             al[mt][0], al[mt][1], al[mt][2], al[mt][3], bh0, bh1);
                    float* c1 = acc[mt][2 * pr + 1];
                    mma16816(c1[0], c1[1], c1[2], c1[3],
                             ah[mt][0], ah[mt][1], ah[mt][2], ah[mt][3], bh2, bh3);
                    mma16816(c1[0], c1[1], c1[2], c1[3],
                             ah[mt][0], ah[mt][1], ah[mt][2], ah[mt][3], bl2, bl3);
                    mma16816(c1[0], c1[1], c1[2], c1[3],
                             al[mt][0], al[mt][1], al[mt][2], al[mt][3], bh2, bh3);
                }
            }
        }
    }

    // ---- epilogue: bias2, LN2 over full 128-col rows, CELU, write h2 ----
#pragma unroll
    for (int mt = 0; mt < 4; mt++) {
        const int rloc = warpM * 64 + mt * 16 + (lane >> 2);
        float s0 = 0.f, q0 = 0.f, s1 = 0.f, q1 = 0.f;
#pragma unroll
        for (int nt = 0; nt < 4; nt++) {
            const int col = warpN * 32 + nt * 8 + (lane & 3) * 2;
            const float b0 = sb2[col], b1 = sb2[col + 1];
            float* c = acc[mt][nt];
            const float v00 = c[0] + b0, v01 = c[1] + b1;
            const float v10 = c[2] + b0, v11 = c[3] + b1;
            s0 += v00 + v01; q0 += v00 * v00 + v01 * v01;
            s1 += v10 + v11; q1 += v10 * v10 + v11 * v11;
        }
#pragma unroll
        for (int o = 1; o <= 2; o <<= 1) {
            s0 += __shfl_xor_sync(0xffffffffu, s0, o);
            q0 += __shfl_xor_sync(0xffffffffu, q0, o);
            s1 += __shfl_xor_sync(0xffffffffu, s1, o);
            q1 += __shfl_xor_sync(0xffffffffu, q1, o);
        }
        if ((lane & 3) == 0) {
            sred[warpN][rloc]     = make_float2(s0, q0);
            sred[warpN][rloc + 8] = make_float2(s1, q1);
        }
    }
    __syncthreads();
    if (tid < 128) {
        float s = 0.f, q = 0.f;
#pragma unroll
        for (int w = 0; w < 4; w++) { s += sred[w][tid].x; q += sred[w][tid].y; }
        const float mu = s * (1.f / 128.f);
        smu[tid]   = mu;
        srstd[tid] = rsqrtf(q * (1.f / 128.f) - mu * mu + 1e-5f);
    }
    __syncthreads();
#pragma unroll
    for (int mt = 0; mt < 4; mt++) {
        const int rloc = warpM * 64 + mt * 16 + (lane >> 2);
        const float mu0 = smu[rloc],     rs0 = srstd[rloc];
        const float mu1 = smu[rloc + 8], rs1 = srstd[rloc + 8];
        const size_t r0 = rowBase + rloc;
#pragma unroll
        for (int nt = 0; nt < 4; nt++) {
            const int col = warpN * 32 + nt * 8 + (lane & 3) * 2;
            const float b0 = sb2[col], b1 = sb2[col + 1];
            float* c = acc[mt][nt];
            float y00 = (c[0] + b0 - mu0) * rs0 * sg2[col]     + sbe2[col];
            float y01 = (c[1] + b1 - mu0) * rs0 * sg2[col + 1] + sbe2[col + 1];
            float y10 = (c[2] + b0 - mu1) * rs1 * sg2[col]     + sbe2[col];
            float y11 = (c[3] + b1 - mu1) * rs1 * sg2[col + 1] + sbe2[col + 1];
            *reinterpret_cast<float2*>(h2 + r0 * 128 + col) =
                make_float2(celu1(y00), celu1(y01));
            *reinterpret_cast<float2*>(h2 + (r0 + 8) * 128 + col) =
                make_float2(celu1(y10), celu1(y11));
        }
    }
}

// ---------------------------------------------------------------------------
// Tail: layer3 (128->32)+LN+CELU, layer4 (32->8)+LN+CELU, spectral-norm head.
// ---------------------------------------------------------------------------
__global__ void __launch_bounds__(256)
tail_kernel(const float* __restrict__ h2,
            const float* __restrict__ W3, const float* __restrict__ b3,
            const float* __restrict__ g3, const float* __restrict__ be3,
            const float* __restrict__ W4, const float* __restrict__ b4,
            const float* __restrict__ g4, const float* __restrict__ be4,
            const float* __restrict__ Wh, const float* __restrict__ bh,
            const float* __restrict__ u, float* __restrict__ out)
{
    __shared__ float sW3[32 * 128];
    __shared__ float sW4[8 * 32];
    const int tid = threadIdx.x;
    for (int i = tid; i < 32 * 128; i += 256) sW3[i] = W3[i];
    if (tid < 8 * 32) sW4[tid] = W4[tid];
    __syncthreads();

    const int lane = tid & 31;
    const size_t row = (size_t)blockIdx.x * 8 + (tid >> 5);
    const float* rp = h2 + row * 128;
    const float r0 = rp[lane], r1 = rp[lane + 32], r2 = rp[lane + 64], r3 = rp[lane + 96];

    float h3 = 0.f;
#pragma unroll
    for (int j = 0; j < 32; j++) {
        const float* w = sW3 + j * 128;
        float p = r0 * w[lane] + r1 * w[lane + 32] + r2 * w[lane + 64] + r3 * w[lane + 96];
        p = warp_sum(p);
        if (lane == j) h3 = p + b3[j];
    }
    float mu  = warp_sum(h3) * (1.f / 32.f);
    float d   = h3 - mu;
    float var = warp_sum(d * d) * (1.f / 32.f);
    float y3  = d * rsqrtf(var + 1e-5f) * g3[lane] + be3[lane];
    const float c3 = (y3 > 0.f) ? y3 : expm1f(y3);

    float h4 = 0.f;
#pragma unroll
    for (int j = 0; j < 8; j++) {
        float p = warp_sum(c3 * sW4[j * 32 + lane]);
        if (lane == j) h4 = p + b4[j];
    }
    const bool act = (lane < 8);
    float hv = act ? h4 : 0.f;
    mu  = warp_sum(hv) * 0.125f;
    d   = act ? (h4 - mu) : 0.f;
    var = warp_sum(d * d) * 0.125f;
    float c4 = 0.f;
    if (act) {
        float y4 = d * rsqrtf(var + 1e-5f) * g4[lane] + be4[lane];
        c4 = (y4 > 0.f) ? y4 : expm1f(y4);
    }

    const float wh  = act ? Wh[lane] : 0.f;
    const float nrm = sqrtf(warp_sum(wh * wh));
    const float u0  = u[0];
    const float vden = fabsf(u0) * nrm + 1e-12f;
    const float t    = u0 * nrm * nrm / vden;
    const float u2n  = t / (fabsf(t) + 1e-12f);
    const float sigma = u2n * t;

    float p = warp_sum(c4 * wh / sigma);
    if (lane == 0) out[row] = p + bh[0];
}

// ---------------------------------------------------------------------------
extern "C" void kernel_launch(void* const* d_in, const int* in_sizes, int n_in,
                              void* d_out, int out_size)
{
    const float* x   = (const float*)d_in[0];
    const float* W1  = (const float*)d_in[1];
    const float* b1  = (const float*)d_in[2];
    const float* g1  = (const float*)d_in[3];
    const float* be1 = (const float*)d_in[4];
    const float* W2  = (const float*)d_in[5];
    const float* b2  = (const float*)d_in[6];
    const float* g2  = (const float*)d_in[7];
    const float* be2 = (const float*)d_in[8];
    const float* W3  = (const float*)d_in[9];
    const float* b3  = (const float*)d_in[10];
    const float* g3  = (const float*)d_in[11];
    const float* be3 = (const float*)d_in[12];
    const float* W4  = (const float*)d_in[13];
    const float* b4  = (const float*)d_in[14];
    const float* g4  = (const float*)d_in[15];
    const float* be4 = (const float*)d_in[16];
    const float* Wh  = (const float*)d_in[17];
    const float* bh  = (const float*)d_in[18];
    const float* u   = (const float*)d_in[19];
    float* out = (float*)d_out;

    const int M = in_sizes[0] / 512;   // 131072

    __nv_bfloat16 *xhi, *xlo, *w1hi, *w1lo, *w2hi, *w2lo;
    float *h1raw, *h2;
    float2* part;
    cudaGetSymbolAddress((void**)&xhi,   g_xhi);
    cudaGetSymbolAddress((void**)&xlo,   g_xlo);
    cudaGetSymbolAddress((void**)&h1raw, g_h1raw);
    cudaGetSymbolAddress((void**)&h2,    g_h2);
    cudaGetSymbolAddress((void**)&part,  g_part);
    cudaGetSymbolAddress((void**)&w1hi,  g_w1hi);
    cudaGetSymbolAddress((void**)&w1lo,  g_w1lo);
    cudaGetSymbolAddress((void**)&w2hi,  g_w2hi);
    cudaGetSymbolAddress((void**)&w2lo,  g_w2lo);

    constexpr int SMEM1 = 3 * 4 * 128 * 64;    // 98304 (3-stage ring)
    constexpr int SMEM2 = 2 * 49152;           // 98304 (2-stage, with staging)
    cudaFuncSetAttribute(hgemm3_kernel,
                         cudaFuncAttributeMaxDynamicSharedMemorySize, SMEM1);
    cudaFuncSetAttribute(gemm2_fused_kernel,
                         cudaFuncAttributeMaxDynamicSharedMemorySize, SMEM2);

    // Split inputs to bf16 hi/lo
    const int n4x = M * 512 / 4;
    split_kernel<<<(n4x + 255) / 256, 256>>>(x, xhi, xlo, n4x);
    split_kernel<<<(512 * 512 / 4 + 255) / 256, 256>>>(W1, w1hi, w1lo, 512 * 512 / 4);
    split_kernel<<<(128 * 512 / 4 + 255) / 256, 256>>>(W2, w2hi, w2lo, 128 * 512 / 4);

    // Layer 1: GEMM -> h1raw fp32 + per-colblock LN partials
    hgemm3_kernel<<<dim3(4, M / 128), 256, SMEM1>>>(
        xhi, xlo, w1hi, w1lo, b1, h1raw, part, 512, M);

    // Layer 2 fused: LN1+CELU+split (prologue) -> GEMM -> LN2+CELU (epilogue)
    gemm2_fused_kernel<<<M / 128, 256, SMEM2>>>(
        h1raw, part, g1, be1, w2hi, w2lo, b2, g2, be2, h2, M);

    // Layers 3+4 + spectral-norm head
    tail_kernel<<<M / 8, 256>>>(h2, W3, b3, g3, be3, W4, b4, g4, be4, Wh, bh, u, out);
}